// round 11
// baseline (speedup 1.0000x reference)
#include <cuda_runtime.h>
#include <cuda_fp16.h>
#include <cstdint>
#include <math.h>

// ---------------------------------------------------------------------------
// TinyTransformerBlock, sm_103 plain-target tensor path.
// R11: int8 dual-split (3-product) GEMMs for q/k projections via mma.m16n8k32.s8;
//      scores restored to fp16-x3 (split q,k); x1 fp16 V/FFN chain; hi-only aux.
// ---------------------------------------------------------------------------

#define BB   4
#define SS   2048
#define DD   1024
#define DFF_ 4096
#define MM   (BB * SS)      // 8192

typedef __half h16;

// ---- scratch (bss) ----
__device__ h16 g_xh[(size_t)MM * DD];                              // x hi (v-proj)
__device__ signed char g_xq1[(size_t)MM * DD], g_xq2[(size_t)MM * DD];
__device__ float g_xs[MM];
__device__ signed char g_wqq1[(size_t)DD * DD], g_wqq2[(size_t)DD * DD];
__device__ float g_wqs[DD];
__device__ signed char g_wkq1[(size_t)DD * DD], g_wkq2[(size_t)DD * DD];
__device__ float g_wks[DD];
__device__ h16 g_qh[(size_t)MM * DD], g_ql[(size_t)MM * DD];
__device__ h16 g_kh[(size_t)MM * DD], g_kl[(size_t)MM * DD];
__device__ float g_v[(size_t)MM * DD];
__device__ h16 g_vTh[(size_t)MM * DD];
__device__ float g_s[(size_t)BB * SS * SS];     // scores; early: transpose scratch
__device__ h16 g_sh[(size_t)BB * SS * SS];
__device__ h16 g_ah[(size_t)MM * DD];
__device__ h16 g_ph[(size_t)MM * DD];
__device__ h16 g_hh[(size_t)MM * DFF_];
__device__ h16 g_wvh[(size_t)DD * DD];
__device__ h16 g_woh[(size_t)DD * DD];
__device__ h16 g_w1h[(size_t)DFF_ * DD];        // [DFF,D]
__device__ h16 g_w2h[(size_t)DD * DFF_];        // [D,DFF]

// ---------------------------------------------------------------------------
__device__ __forceinline__ uint32_t smem_u32(const void* p) {
    uint32_t a;
    asm("{ .reg .u64 t; cvta.to.shared.u64 t, %1; cvt.u32.u64 %0, t; }" : "=r"(a) : "l"(p));
    return a;
}

__device__ __forceinline__ uint32_t packh2(float x0, float x1) {
    __half2 t = __floats2half2_rn(x0, x1);
    return *(uint32_t*)&t;
}

__device__ __forceinline__ void hsplit2(float x0, float x1, uint32_t& h, uint32_t& l) {
    h = packh2(x0, x1);
    __half2 hv = *(__half2*)&h;
    float2 f = __half22float2(hv);
    l = packh2(x0 - f.x, x1 - f.y);
}

#define CP_ASYNC16(sa, gp) \
    asm volatile("cp.async.cg.shared.global [%0], [%1], 16;" :: "r"(sa), "l"(gp))
#define CP_COMMIT() asm volatile("cp.async.commit_group;")
#define CP_WAIT(n)  asm volatile("cp.async.wait_group %0;" :: "n"(n))

#define LDM_X4(r, sa) \
    asm volatile("ldmatrix.sync.aligned.m8n8.x4.shared.b16 {%0,%1,%2,%3}, [%4];" \
                 : "=r"((r)[0]), "=r"((r)[1]), "=r"((r)[2]), "=r"((r)[3]) : "r"(sa))

__device__ __forceinline__ void mma_f16(float* c, const uint32_t* a, uint32_t b0, uint32_t b1) {
    asm volatile(
        "mma.sync.aligned.m16n8k16.row.col.f32.f16.f16.f32 "
        "{%0,%1,%2,%3}, {%4,%5,%6,%7}, {%8,%9}, {%0,%1,%2,%3};"
        : "+f"(c[0]), "+f"(c[1]), "+f"(c[2]), "+f"(c[3])
        : "r"(a[0]), "r"(a[1]), "r"(a[2]), "r"(a[3]), "r"(b0), "r"(b1));
}

__device__ __forceinline__ void mma_i8(int* c, const uint32_t* a, uint32_t b0, uint32_t b1) {
    asm volatile(
        "mma.sync.aligned.m16n8k32.row.col.s32.s8.s8.s32 "
        "{%0,%1,%2,%3}, {%4,%5,%6,%7}, {%8,%9}, {%0,%1,%2,%3};"
        : "+r"(c[0]), "+r"(c[1]), "+r"(c[2]), "+r"(c[3])
        : "r"(a[0]), "r"(a[1]), "r"(a[2]), "r"(a[3]), "r"(b0), "r"(b1));
}

// ---------------------------------------------------------------------------
// fp16 GEMM (unchanged from R10): C = A @ B^T, split operands.
// NPROD=3: 2-stage.  NPROD<=2: 3-stage, single barrier.
// EP: 0 fp32; 1 relu+hi; 2 fp32+R; 3 split; 4 hi.
// ---------------------------------------------------------------------------
#define PITCH 80
#define TILEB (128 * PITCH)

template <int EP, int NPROD>
__global__ void __launch_bounds__(256, 2)
gemm_mma(const h16* __restrict__ Ah, const h16* __restrict__ Al,
         const h16* __restrict__ Bh, const h16* __restrict__ Bl,
         float* __restrict__ C, h16* __restrict__ Ch, h16* __restrict__ Cl,
         const float* __restrict__ R,
         int M, int N, int K, size_t sA, size_t sB, size_t sC)
{
    constexpr int AH_OFF = 0;
    constexpr int AL_OFF = TILEB;
    constexpr int BH_OFF = (NPROD == 3 ? 2 : 1) * TILEB;
    constexpr int BL_OFF = BH_OFF + TILEB;
    constexpr int NTILES = (NPROD == 3 ? 4 : (NPROD == 2 ? 3 : 2));
    constexpr int BUFB = NTILES * TILEB;
    constexpr int NSTAGES = (NPROD == 3) ? 2 : 3;

    extern __shared__ char smem_raw[];
    const uint32_t sbase = smem_u32(smem_raw);

    const int z = blockIdx.z;
    Ah += z * sA;
    if (NPROD == 3) Al += z * sA;
    Bh += z * sB;
    if (NPROD >= 2) Bl += z * sB;
    if (EP == 0 || EP == 2) C += z * sC;
    else { Ch += z * sC; if (EP == 3) Cl += z * sC; }

    const int n0 = blockIdx.x * 128;
    const int m0 = blockIdx.y * 128;
    const int tid = threadIdx.x;
    const int lane = tid & 31;
    const int warp = tid >> 5;
    const int wm = warp >> 1;
    const int wn = warp & 1;

    const int KC = K / 32;
    const int lr = tid >> 2;
    const int lcb = (tid & 3) * 16;

    auto issue = [&](int c) {
        const uint32_t sb = sbase + (c % NSTAGES) * BUFB;
        const size_t ke = (size_t)c * 32;
#pragma unroll
        for (int pass = 0; pass < 2; pass++) {
            const int r = lr + pass * 64;
            const uint32_t so = (uint32_t)r * PITCH + lcb;
            CP_ASYNC16(sb + AH_OFF + so, (const char*)(Ah + (size_t)(m0 + r) * K + ke) + lcb);
            if (NPROD == 3)
                CP_ASYNC16(sb + AL_OFF + so, (const char*)(Al + (size_t)(m0 + r) * K + ke) + lcb);
            CP_ASYNC16(sb + BH_OFF + so, (const char*)(Bh + (size_t)(n0 + r) * K + ke) + lcb);
            if (NPROD >= 2)
                CP_ASYNC16(sb + BL_OFF + so, (const char*)(Bl + (size_t)(n0 + r) * K + ke) + lcb);
        }
        CP_COMMIT();
    };

    float c[2][8][4];
#pragma unroll
    for (int i = 0; i < 2; i++)
#pragma unroll
        for (int j = 0; j < 8; j++)
#pragma unroll
            for (int t = 0; t < 4; t++) c[i][j][t] = 0.f;

    const int lrow = (lane & 7) | ((lane >> 3) & 1) << 3;
    const int lcol = (lane >> 4) * 8;

    auto compute = [&](int cc) {
        const uint32_t sb = sbase + (cc % NSTAGES) * BUFB;
#pragma unroll
        for (int k0 = 0; k0 < 32; k0 += 16) {
            uint32_t ah[2][4], al[2][4];
#pragma unroll
            for (int mt = 0; mt < 2; mt++) {
                const uint32_t ra = (uint32_t)(wm * 32 + mt * 16 + lrow) * PITCH + (k0 + lcol) * 2;
                LDM_X4(ah[mt], sb + AH_OFF + ra);
                if (NPROD == 3) LDM_X4(al[mt], sb + AL_OFF + ra);
            }
#pragma unroll
            for (int nt2 = 0; nt2 < 4; nt2++) {
                uint32_t bh[4], bl[4];
                const uint32_t rb = (uint32_t)(wn * 64 + nt2 * 16 + lrow) * PITCH + (k0 + lcol) * 2;
                LDM_X4(bh, sb + BH_OFF + rb);
                if (NPROD >= 2) LDM_X4(bl, sb + BL_OFF + rb);
#pragma unroll
                for (int sel = 0; sel < 2; sel++) {
                    const int nt = nt2 * 2 + sel;
                    mma_f16(c[0][nt], ah[0], bh[sel], bh[2 + sel]);
                    mma_f16(c[1][nt], ah[1], bh[sel], bh[2 + sel]);
                }
                if (NPROD >= 2) {
#pragma unroll
                    for (int sel = 0; sel < 2; sel++) {
                        const int nt = nt2 * 2 + sel;
                        mma_f16(c[0][nt], ah[0], bl[sel], bl[2 + sel]);
                        mma_f16(c[1][nt], ah[1], bl[sel], bl[2 + sel]);
                    }
                }
                if (NPROD == 3) {
#pragma unroll
                    for (int sel = 0; sel < 2; sel++) {
                        const int nt = nt2 * 2 + sel;
                        mma_f16(c[0][nt], al[0], bh[sel], bh[2 + sel]);
                        mma_f16(c[1][nt], al[1], bh[sel], bh[2 + sel]);
                    }
                }
            }
        }
    };

    if (NSTAGES == 2) {
        issue(0);
        for (int cc = 0; cc < KC; cc++) {
            if (cc + 1 < KC) { issue(cc + 1); CP_WAIT(1); }
            else             { CP_WAIT(0); }
            __syncthreads();
            compute(cc);
            __syncthreads();
        }
    } else {
        issue(0);
        issue(1);
        for (int cc = 0; cc < KC; cc++) {
            if (cc < KC - 1) { CP_WAIT(1); } else { CP_WAIT(0); }
            __syncthreads();
            if (cc + 2 < KC) issue(cc + 2);
            compute(cc);
        }
    }

    const int qrow = lane >> 2;
    const int qcol = (lane & 3) * 2;
#pragma unroll
    for (int mt = 0; mt < 2; mt++) {
#pragma unroll
        for (int nt = 0; nt < 8; nt++) {
            const int row0 = m0 + wm * 32 + mt * 16 + qrow;
            const int col = n0 + wn * 64 + nt * 8 + qcol;
            const float* f = c[mt][nt];
#pragma unroll
            for (int h = 0; h < 2; h++) {
                const int row = row0 + h * 8;
                float v0 = f[2 * h], v1 = f[2 * h + 1];
                if (EP == 0) {
                    *(float2*)(C + (size_t)row * N + col) = make_float2(v0, v1);
                } else if (EP == 2) {
                    const float2 r2 = *(const float2*)(R + (size_t)row * N + col);
                    *(float2*)(C + (size_t)row * N + col) = make_float2(v0 + r2.x, v1 + r2.y);
                } else if (EP == 3) {
                    uint32_t hw, lw;
                    hsplit2(v0, v1, hw, lw);
                    *(uint32_t*)(Ch + (size_t)row * N + col) = hw;
                    *(uint32_t*)(Cl + (size_t)row * N + col) = lw;
                } else {
                    if (EP == 1) { v0 = fmaxf(v0, 0.f); v1 = fmaxf(v1, 0.f); }
                    *(uint32_t*)(Ch + (size_t)row * N + col) = packh2(v0, v1);
                }
            }
        }
    }
}

// ---------------------------------------------------------------------------
// int8 dual-split GEMM: C[M,N] = dequant( A @ B^T ), A,B int8 two-level.
// x ~= q1*s1 + q2*(s1/256).  C = sA*sB*(Q + P/256), Q = A1B1, P = A1B2 + A2B1.
// Tile 128x64, k-chunk 64, 3-stage single-barrier. Output: split fp16 (Ch,Cl).
// ---------------------------------------------------------------------------
#define IPITCH 80
#define IA_BYTES (128 * IPITCH)
#define IB_BYTES (64 * IPITCH)
#define ISTAGE (2 * IA_BYTES + 2 * IB_BYTES)   // 30720
#define ISMEM (3 * ISTAGE)                      // 92160

__global__ void __launch_bounds__(256, 2)
gemm_i8(const signed char* __restrict__ A1, const signed char* __restrict__ A2,
        const float* __restrict__ SA,
        const signed char* __restrict__ B1, const signed char* __restrict__ B2,
        const float* __restrict__ SB,
        h16* __restrict__ Ch, h16* __restrict__ Cl,
        int M, int N, int K)
{
    extern __shared__ char smem_raw[];
    const uint32_t sbase = smem_u32(smem_raw);

    const int n0 = blockIdx.x * 64;
    const int m0 = blockIdx.y * 128;
    const int tid = threadIdx.x;
    const int lane = tid & 31;
    const int warp = tid >> 5;
    const int wm = warp >> 1;       // m offset 32*wm
    const int wn = warp & 1;        // n offset 32*wn

    const int KC = K / 64;
    const int lr = tid >> 2;            // 0..63
    const int lcb = (tid & 3) * 16;     // 0..48

    auto issue = [&](int c) {
        const uint32_t sb = sbase + (c % 3) * ISTAGE;
        const size_t ke = (size_t)c * 64;
#pragma unroll
        for (int pass = 0; pass < 2; pass++) {
            const int r = lr + pass * 64;
            const uint32_t so = (uint32_t)r * IPITCH + lcb;
            CP_ASYNC16(sb + so,            A1 + (size_t)(m0 + r) * K + ke + lcb);
            CP_ASYNC16(sb + IA_BYTES + so, A2 + (size_t)(m0 + r) * K + ke + lcb);
        }
        {
            const uint32_t so = (uint32_t)lr * IPITCH + lcb;
            CP_ASYNC16(sb + 2 * IA_BYTES + so,            B1 + (size_t)(n0 + lr) * K + ke + lcb);
            CP_ASYNC16(sb + 2 * IA_BYTES + IB_BYTES + so, B2 + (size_t)(n0 + lr) * K + ke + lcb);
        }
        CP_COMMIT();
    };

    int cq[2][4][4], cp[2][4][4];
#pragma unroll
    for (int i = 0; i < 2; i++)
#pragma unroll
        for (int j = 0; j < 4; j++)
#pragma unroll
            for (int t = 0; t < 4; t++) { cq[i][j][t] = 0; cp[i][j][t] = 0; }

    const int lrow = (lane & 7) | ((lane >> 3) & 1) << 3;   // 0..15
    const int lcol = (lane >> 4) * 8;                       // 0 or 8 (b16 cols)

    auto compute = [&](int cc) {
        const uint32_t sb = sbase + (cc % 3) * ISTAGE;
#pragma unroll
        for (int k0 = 0; k0 < 64; k0 += 32) {
            uint32_t a1[2][4], a2[2][4], b1[2][4], b2[2][4];
#pragma unroll
            for (int mt = 0; mt < 2; mt++) {
                const uint32_t ra = (uint32_t)(wm * 32 + mt * 16 + lrow) * IPITCH + k0 + lcol * 2;
                LDM_X4(a1[mt], sb + ra);
                LDM_X4(a2[mt], sb + IA_BYTES + ra);
            }
#pragma unroll
            for (int nt2 = 0; nt2 < 2; nt2++) {
                const uint32_t rb = (uint32_t)(wn * 32 + nt2 * 16 + lrow) * IPITCH + k0 + lcol * 2;
                LDM_X4(b1[nt2], sb + 2 * IA_BYTES + rb);
                LDM_X4(b2[nt2], sb + 2 * IA_BYTES + IB_BYTES + rb);
            }
            // product-major: Q = A1B1; P = A1B2 + A2B1
#pragma unroll
            for (int mt = 0; mt < 2; mt++)
#pragma unroll
                for (int nt2 = 0; nt2 < 2; nt2++)
#pragma unroll
                    for (int sel = 0; sel < 2; sel++)
                        mma_i8(cq[mt][nt2 * 2 + sel], a1[mt], b1[nt2][sel], b1[nt2][2 + sel]);
#pragma unroll
            for (int mt = 0; mt < 2; mt++)
#pragma unroll
                for (int nt2 = 0; nt2 < 2; nt2++)
#pragma unroll
                    for (int sel = 0; sel < 2; sel++)
                        mma_i8(cp[mt][nt2 * 2 + sel], a1[mt], b2[nt2][sel], b2[nt2][2 + sel]);
#pragma unroll
            for (int mt = 0; mt < 2; mt++)
#pragma unroll
                for (int nt2 = 0; nt2 < 2; nt2++)
#pragma unroll
                    for (int sel = 0; sel < 2; sel++)
                        mma_i8(cp[mt][nt2 * 2 + sel], a2[mt], b1[nt2][sel], b1[nt2][2 + sel]);
        }
    };

    issue(0);
    issue(1);
    for (int cc = 0; cc < KC; cc++) {
        if (cc < KC - 1) { CP_WAIT(1); } else { CP_WAIT(0); }
        __syncthreads();
        if (cc + 2 < KC) issue(cc + 2);
        compute(cc);
    }

    // epilogue: dequant + split-fp16 store
    const int qrow = lane >> 2;
    const int qcol = (lane & 3) * 2;
#pragma unroll
    for (int mt = 0; mt < 2; mt++) {
#pragma unroll
        for (int nt = 0; nt < 4; nt++) {
            const int row0 = m0 + wm * 32 + mt * 16 + qrow;
            const int col = n0 + wn * 32 + nt * 8 + qcol;
            const float sb0 = SB[col], sb1 = SB[col + 1];
            const int* fq = cq[mt][nt];
            const int* fp = cp[mt][nt];
#pragma unroll
            for (int h = 0; h < 2; h++) {
                const int row = row0 + h * 8;
                const float sa = SA[row];
                const float v0 = sa * sb0 * ((float)fq[2 * h]     + (float)fp[2 * h]     * (1.f / 256.f));
                const float v1 = sa * sb1 * ((float)fq[2 * h + 1] + (float)fp[2 * h + 1] * (1.f / 256.f));
                uint32_t hw, lw;
                hsplit2(v0, v1, hw, lw);
                *(uint32_t*)(Ch + (size_t)row * N + col) = hw;
                *(uint32_t*)(Cl + (size_t)row * N + col) = lw;
            }
        }
    }
}

// ---------------------------------------------------------------------------
// per-row two-level int8 quantization (K = 1024, 256 threads, 1 float4/thread)
// ---------------------------------------------------------------------------
__global__ void quant_rows(const float* __restrict__ in, signed char* __restrict__ q1,
                           signed char* __restrict__ q2, float* __restrict__ scale, int K)
{
    const int row = blockIdx.x;
    const int t = threadIdx.x;
    const float4 v = ((const float4*)(in + (size_t)row * K))[t];

    float am = fmaxf(fmaxf(fabsf(v.x), fabsf(v.y)), fmaxf(fabsf(v.z), fabsf(v.w)));
#pragma unroll
    for (int o = 16; o > 0; o >>= 1) am = fmaxf(am, __shfl_xor_sync(0xffffffffu, am, o));
    __shared__ float red[8];
    if ((t & 31) == 0) red[t >> 5] = am;
    __syncthreads();
    float amax = red[0];
#pragma unroll
    for (int i = 1; i < 8; i++) amax = fmaxf(amax, red[i]);
    if (amax < 1e-30f) amax = 1e-30f;

    const float s1 = amax * (1.f / 127.f);
    const float inv1 = 127.f / amax;
    int a[4]; float x[4] = {v.x, v.y, v.z, v.w};
    signed char c1[4], c2[4];
#pragma unroll
    for (int i = 0; i < 4; i++) {
        a[i] = (int)rintf(x[i] * inv1);
        a[i] = min(127, max(-127, a[i]));
        const float r = x[i] - a[i] * s1;
        int b = (int)rintf(r * (256.f * inv1));
        b = min(127, max(-127, b));
        c1[i] = (signed char)a[i];
        c2[i] = (signed char)b;
    }
    *(char4*)(q1 + (size_t)row * K + t * 4) = make_char4(c1[0], c1[1], c1[2], c1[3]);
    *(char4*)(q2 + (size_t)row * K + t * 4) = make_char4(c2[0], c2[1], c2[2], c2[3]);
    if (t == 0) scale[row] = s1;
}

// ---------------------------------------------------------------------------
// fp32 transpose (for weight pre-pass)
// ---------------------------------------------------------------------------
__global__ void ttrans_k(const float* __restrict__ in, float* __restrict__ out, int Rr, int Cc)
{
    __shared__ float tbuf[32][33];
    const int c0 = blockIdx.x * 32, r0 = blockIdx.y * 32;
    const int tx = threadIdx.x, ty = threadIdx.y;
#pragma unroll
    for (int i = 0; i < 32; i += 8)
        tbuf[ty + i][tx] = in[(size_t)(r0 + ty + i) * Cc + c0 + tx];
    __syncthreads();
#pragma unroll
    for (int i = 0; i < 32; i += 8)
        out[(size_t)(c0 + ty + i) * Rr + r0 + tx] = tbuf[tx][ty + i];
}

// ---------------------------------------------------------------------------
// transpose fp32 -> fp16 hi only, batched
// ---------------------------------------------------------------------------
__global__ void thalf_k(const float* __restrict__ in, h16* __restrict__ oh,
                        int Rr, int Cc, size_t sin, size_t sout)
{
    __shared__ float tbuf[32][33];
    const int z = blockIdx.z;
    in += z * sin; oh += z * sout;
    const int c0 = blockIdx.x * 32, r0 = blockIdx.y * 32;
    const int tx = threadIdx.x, ty = threadIdx.y;
#pragma unroll
    for (int i = 0; i < 32; i += 8)
        tbuf[ty + i][tx] = in[(size_t)(r0 + ty + i) * Cc + c0 + tx];
    __syncthreads();
#pragma unroll
    for (int i = 0; i < 32; i += 8)
        oh[(size_t)(c0 + ty + i) * Rr + r0 + tx] = __float2half_rn(tbuf[tx][ty + i]);
}

// ---------------------------------------------------------------------------
// elementwise fp32 -> fp16 hi
// ---------------------------------------------------------------------------
__global__ void half_k(const float* __restrict__ in, h16* __restrict__ oh, size_t n4)
{
    const size_t i = (size_t)blockIdx.x * blockDim.x + threadIdx.x;
    if (i >= n4) return;
    const float4 v = ((const float4*)in)[i];
    ((uint2*)oh)[i] = make_uint2(packh2(v.x, v.y), packh2(v.z, v.w));
}

// ---------------------------------------------------------------------------
// softmax rows (n=2048), warp-shuffle reductions, hi-only fp16 out
// ---------------------------------------------------------------------------
__global__ void softmax_k(const float* __restrict__ S, h16* __restrict__ oh, int n)
{
    const size_t ro = (size_t)blockIdx.x * n;
    const float* row = S + ro;
    const int t = threadIdx.x;
    const int lane = t & 31, w = t >> 5;
    __shared__ float red[8];

    float v[8];
    {
        const float4 x0 = *(const float4*)(row + t * 8);
        const float4 x1 = *(const float4*)(row + t * 8 + 4);
        v[0] = x0.x; v[1] = x0.y; v[2] = x0.z; v[3] = x0.w;
        v[4] = x1.x; v[5] = x1.y; v[6] = x1.z; v[7] = x1.w;
    }
    float m = v[0];
#pragma unroll
    for (int i = 1; i < 8; i++) m = fmaxf(m, v[i]);
#pragma unroll
    for (int o = 16; o > 0; o >>= 1) m = fmaxf(m, __shfl_xor_sync(0xffffffffu, m, o));
    if (lane == 0) red[w] = m;
    __syncthreads();
    float M = red[0];
#pragma unroll
    for (int i = 1; i < 8; i++) M = fmaxf(M, red[i]);
    __syncthreads();

    float sum = 0.f;
#pragma unroll
    for (int i = 0; i < 8; i++) { v[i] = expf(v[i] - M); sum += v[i]; }
#pragma unroll
    for (int o = 16; o > 0; o >>= 1) sum += __shfl_xor_sync(0xffffffffu, sum, o);
    if (lane == 0) red[w] = sum;
    __syncthreads();
    float Sm = red[0];
#pragma unroll
    for (int i = 1; i < 8; i++) Sm += red[i];
    const float inv = 1.f / Sm;

    uint32_t hw[4];
#pragma unroll
    for (int i = 0; i < 4; i++)
        hw[i] = packh2(v[2 * i] * inv, v[2 * i + 1] * inv);
    *(uint4*)(oh + ro + t * 8) = make_uint4(hw[0], hw[1], hw[2], hw[3]);
}

// ---------------------------------------------------------------------------
extern "C" void kernel_launch(void* const* d_in, const int* in_sizes, int n_in,
                              void* d_out, int out_size)
{
    const float* x  = (const float*)d_in[0];
    const float* wq = (const float*)d_in[1];
    const float* wk = (const float*)d_in[2];
    const float* wv = (const float*)d_in[3];
    const float* wo = (const float*)d_in[4];
    const float* w1 = (const float*)d_in[5];
    const float* w2 = (const float*)d_in[6];
    float* out = (float*)d_out;

#define SYM(T, p, g) T p; cudaGetSymbolAddress((void**)&p, g)
    SYM(h16*, xh, g_xh);
    SYM(signed char*, xq1, g_xq1); SYM(signed char*, xq2, g_xq2); SYM(float*, xs, g_xs);
    SYM(signed char*, wqq1, g_wqq1); SYM(signed char*, wqq2, g_wqq2); SYM(float*, wqs, g_wqs);
    SYM(signed char*, wkq1, g_wkq1); SYM(signed char*, wkq2, g_wkq2); SYM(float*, wks, g_wks);
    SYM(h16*, qh, g_qh); SYM(h16*, ql, g_ql); SYM(h16*, kh, g_kh); SYM(h16*, kl, g_kl);
    SYM(float*, v, g_v); SYM(h16*, vTh, g_vTh);
    SYM(float*, s, g_s); SYM(h16*, sh, g_sh);
    SYM(h16*, ah, g_ah); SYM(h16*, ph, g_ph); SYM(h16*, hh, g_hh);
    SYM(h16*, wvh, g_wvh); SYM(h16*, woh, g_woh);
    SYM(h16*, w1h, g_w1h); SYM(h16*, w2h, g_w2h);
#undef SYM

    const int GS3 = 2 * 4 * TILEB;    // 81920: fp16 x3, 2-stage
    const int GS1 = 3 * 2 * TILEB;    // 61440: fp16 x1, 3-stage
    cudaFuncSetAttribute(gemm_mma<0, 3>, cudaFuncAttributeMaxDynamicSharedMemorySize, GS3);
    cudaFuncSetAttribute(gemm_mma<0, 1>, cudaFuncAttributeMaxDynamicSharedMemorySize, GS1);
    cudaFuncSetAttribute(gemm_mma<4, 1>, cudaFuncAttributeMaxDynamicSharedMemorySize, GS1);
    cudaFuncSetAttribute(gemm_mma<1, 1>, cudaFuncAttributeMaxDynamicSharedMemorySize, GS1);
    cudaFuncSetAttribute(gemm_mma<2, 1>, cudaFuncAttributeMaxDynamicSharedMemorySize, GS1);
    cudaFuncSetAttribute(gemm_i8, cudaFuncAttributeMaxDynamicSharedMemorySize, ISMEM);

    const size_t sSD = (size_t)SS * DD;
    const size_t sSS2 = (size_t)SS * SS;
    const dim3 tb(32, 8);

    // x: fp16 hi (for v-proj) + int8 two-level quant (for q/k proj)
    half_k<<<(MM * DD / 4 + 255) / 256, 256>>>(x, xh, (size_t)MM * DD / 4);
    quant_rows<<<MM, 256>>>(x, xq1, xq2, xs, DD);

    // wq, wk: transpose (scratch = g_s, consumed before scores) then quantize rows
    ttrans_k<<<dim3(32, 32), tb>>>(wq, s, DD, DD);
    quant_rows<<<DD, 256>>>(s, wqq1, wqq2, wqs, DD);
    ttrans_k<<<dim3(32, 32), tb>>>(wk, s + (size_t)DD * DD, DD, DD);
    quant_rows<<<DD, 256>>>(s + (size_t)DD * DD, wkq1, wkq2, wks, DD);

    // q, k projections (int8 dual-split, split-fp16 out)
    gemm_i8<<<dim3(DD / 64, MM / 128), 256, ISMEM>>>(xq1, xq2, xs, wqq1, wqq2, wqs, qh, ql, MM, DD, DD);
    gemm_i8<<<dim3(DD / 64, MM / 128), 256, ISMEM>>>(xq1, xq2, xs, wkq1, wkq2, wks, kh, kl, MM, DD, DD);

    // v projection (fp16 x1)
    thalf_k<<<dim3(32, 32), tb>>>(wv, wvh, DD, DD, 0, 0);
    gemm_mma<0, 1><<<dim3(8, 64, 1), 256, GS1>>>(xh, nullptr, wvh, nullptr, v, nullptr, nullptr, nullptr, MM, DD, DD, 0, 0, 0);

    // remaining weights (hi-only)
    thalf_k<<<dim3(32, 32), tb>>>(wo, woh, DD, DD, 0, 0);
    thalf_k<<<dim3(DFF_ / 32, DD / 32), tb>>>(w1, w1h, DD, DFF_, 0, 0);   // [DFF,D]
    thalf_k<<<dim3(DD / 32, DFF_ / 32), tb>>>(w2, w2h, DFF_, DD, 0, 0);   // [D,DFF]

    // vT per batch (hi-only)
    thalf_k<<<dim3(DD / 32, SS / 32, BB), tb>>>(v, vTh, SS, DD, sSD, sSD);

    // scores = q @ k^T (fp16 x3, fp32 out)
    gemm_mma<0, 3><<<dim3(16, 16, BB), 256, GS3>>>(qh, ql, kh, kl, s, nullptr, nullptr, nullptr, SS, SS, DD, sSD, sSD, sSS2);

    // softmax (hi out)
    softmax_k<<<MM, 256>>>(s, sh, SS);

    // attn = weights @ v (x1)
    gemm_mma<4, 1><<<dim3(8, 16, BB), 256, GS1>>>(sh, nullptr, vTh, nullptr, nullptr, ah, nullptr, nullptr, SS, DD, SS, sSS2, sSD, sSD);

    // proj = attn @ wo (x1)
    gemm_mma<4, 1><<<dim3(8, 64, 1), 256, GS1>>>(ah, nullptr, woh, nullptr, nullptr, ph, nullptr, nullptr, MM, DD, DD, 0, 0, 0);

    // hidden = relu(proj @ w1) (x1)
    gemm_mma<1, 1><<<dim3(32, 64, 1), 256, GS1>>>(ph, nullptr, w1h, nullptr, nullptr, hh, nullptr, nullptr, MM, DFF_, DD, 0, 0, 0);

    // out = hidden @ w2 + x (x1)
    gemm_mma<2, 1><<<dim3(8, 64, 1), 256, GS1>>>(hh, nullptr, w2h, nullptr, out, nullptr, nullptr, x, MM, DD, DFF_, 0, 0, 0);
}

// round 13
// speedup vs baseline: 1.3058x; 1.3058x over previous
#include <cuda_runtime.h>
#include <cuda_fp16.h>
#include <cstdint>
#include <math.h>

// ---------------------------------------------------------------------------
// TinyTransformerBlock, sm_103 plain-target tensor path.
// R12: revert int8; R10 precision layout (q x3-hi, k x3-split, scores x2,
//      V/FFN x1) + TN=64 tiles (wave-tail fix) + 3-stage everywhere.
// ---------------------------------------------------------------------------

#define BB   4
#define SS   2048
#define DD   1024
#define DFF_ 4096
#define MM   (BB * SS)      // 8192

typedef __half h16;

// ---- scratch (bss) ----
__device__ h16 g_xh[(size_t)MM * DD], g_xl[(size_t)MM * DD];
__device__ h16 g_qh[(size_t)MM * DD];
__device__ h16 g_kh[(size_t)MM * DD], g_kl[(size_t)MM * DD];
__device__ float g_v[(size_t)MM * DD];
__device__ h16 g_vTh[(size_t)MM * DD];
__device__ float g_s[(size_t)BB * SS * SS];
__device__ h16 g_sh[(size_t)BB * SS * SS];
__device__ h16 g_ah[(size_t)MM * DD];
__device__ h16 g_ph[(size_t)MM * DD];
__device__ h16 g_hh[(size_t)MM * DFF_];
__device__ h16 g_wqh[(size_t)DD * DD], g_wql[(size_t)DD * DD];
__device__ h16 g_wkh[(size_t)DD * DD], g_wkl[(size_t)DD * DD];
__device__ h16 g_wvh[(size_t)DD * DD];
__device__ h16 g_woh[(size_t)DD * DD];
__device__ h16 g_w1h[(size_t)DFF_ * DD];        // [DFF,D]
__device__ h16 g_w2h[(size_t)DD * DFF_];        // [D,DFF]

// ---------------------------------------------------------------------------
__device__ __forceinline__ uint32_t smem_u32(const void* p) {
    uint32_t a;
    asm("{ .reg .u64 t; cvta.to.shared.u64 t, %1; cvt.u32.u64 %0, t; }" : "=r"(a) : "l"(p));
    return a;
}

__device__ __forceinline__ uint32_t packh2(float x0, float x1) {
    __half2 t = __floats2half2_rn(x0, x1);
    return *(uint32_t*)&t;
}

__device__ __forceinline__ void hsplit2(float x0, float x1, uint32_t& h, uint32_t& l) {
    h = packh2(x0, x1);
    __half2 hv = *(__half2*)&h;
    float2 f = __half22float2(hv);
    l = packh2(x0 - f.x, x1 - f.y);
}

#define CP_ASYNC16(sa, gp) \
    asm volatile("cp.async.cg.shared.global [%0], [%1], 16;" :: "r"(sa), "l"(gp))
#define CP_COMMIT() asm volatile("cp.async.commit_group;")
#define CP_WAIT(n)  asm volatile("cp.async.wait_group %0;" :: "n"(n))

#define LDM_X4(r, sa) \
    asm volatile("ldmatrix.sync.aligned.m8n8.x4.shared.b16 {%0,%1,%2,%3}, [%4];" \
                 : "=r"((r)[0]), "=r"((r)[1]), "=r"((r)[2]), "=r"((r)[3]) : "r"(sa))

__device__ __forceinline__ void mma_f16(float* c, const uint32_t* a, uint32_t b0, uint32_t b1) {
    asm volatile(
        "mma.sync.aligned.m16n8k16.row.col.f32.f16.f16.f32 "
        "{%0,%1,%2,%3}, {%4,%5,%6,%7}, {%8,%9}, {%0,%1,%2,%3};"
        : "+f"(c[0]), "+f"(c[1]), "+f"(c[2]), "+f"(c[3])
        : "r"(a[0]), "r"(a[1]), "r"(a[2]), "r"(a[3]), "r"(b0), "r"(b1));
}

// ---------------------------------------------------------------------------
// fp16 split GEMM: C[M,N] = A[M,K] @ B[N,K]^T.
// NPROD=3: ah*bh + ah*bl + al*bh.  NPROD=2: ah*bh + ah*bl.  NPROD=1: ah*bh.
// TN in {64,128}: N-tile width (M-tile fixed 128).
// EP: 0 fp32; 1 relu+hi; 2 fp32+R; 3 split hi+lo; 4 hi.
// ---------------------------------------------------------------------------
#define PITCH 80
#define ATILE (128 * PITCH)

template <int EP, int NPROD, int TN>
__global__ void __launch_bounds__(256, 2)
gemm_mma(const h16* __restrict__ Ah, const h16* __restrict__ Al,
         const h16* __restrict__ Bh, const h16* __restrict__ Bl,
         float* __restrict__ C, h16* __restrict__ Ch, h16* __restrict__ Cl,
         const float* __restrict__ R,
         int M, int N, int K, size_t sA, size_t sB, size_t sC)
{
    constexpr int BTILE = TN * PITCH;
    constexpr int AH_OFF = 0;
    constexpr int AL_OFF = ATILE;                               // NPROD==3 only
    constexpr int BH_OFF = (NPROD == 3 ? 2 : 1) * ATILE;
    constexpr int BL_OFF = BH_OFF + BTILE;                      // NPROD>=2 only
    constexpr int BUFB = (NPROD == 3 ? 2 : 1) * ATILE + (NPROD >= 2 ? 2 : 1) * BTILE;
    constexpr int NSTAGES = (3 * BUFB <= 94208) ? 3 : 2;
    constexpr int WNC = TN / 2;      // cols per wn half
    constexpr int NT2 = TN / 32;     // 16-col ldmatrix groups per warp
    constexpr int NT  = TN / 16;     // 8-col output tiles per warp

    extern __shared__ char smem_raw[];
    const uint32_t sbase = smem_u32(smem_raw);

    const int z = blockIdx.z;
    Ah += z * sA;
    if (NPROD == 3) Al += z * sA;
    Bh += z * sB;
    if (NPROD >= 2) Bl += z * sB;
    if (EP == 0 || EP == 2) C += z * sC;
    else { Ch += z * sC; if (EP == 3) Cl += z * sC; }

    const int n0 = blockIdx.x * TN;
    const int m0 = blockIdx.y * 128;
    const int tid = threadIdx.x;
    const int lane = tid & 31;
    const int warp = tid >> 5;
    const int wm = warp >> 1;        // m offset 32*wm
    const int wn = warp & 1;         // n offset WNC*wn

    const int KC = K / 32;
    const int lr = tid >> 2;             // 0..63
    const int lcb = (tid & 3) * 16;      // byte offset in 64B k-row

    auto issue = [&](int c) {
        const uint32_t sb = sbase + (c % NSTAGES) * BUFB;
        const size_t ke = (size_t)c * 32;
#pragma unroll
        for (int pass = 0; pass < 2; pass++) {
            const int r = lr + pass * 64;
            const uint32_t so = (uint32_t)r * PITCH + lcb;
            CP_ASYNC16(sb + AH_OFF + so, (const char*)(Ah + (size_t)(m0 + r) * K + ke) + lcb);
            if (NPROD == 3)
                CP_ASYNC16(sb + AL_OFF + so, (const char*)(Al + (size_t)(m0 + r) * K + ke) + lcb);
        }
#pragma unroll
        for (int pass = 0; pass < TN / 64; pass++) {
            const int r = lr + pass * 64;
            const uint32_t so = (uint32_t)r * PITCH + lcb;
            CP_ASYNC16(sb + BH_OFF + so, (const char*)(Bh + (size_t)(n0 + r) * K + ke) + lcb);
            if (NPROD >= 2)
                CP_ASYNC16(sb + BL_OFF + so, (const char*)(Bl + (size_t)(n0 + r) * K + ke) + lcb);
        }
        CP_COMMIT();
    };

    float c[2][NT][4];
#pragma unroll
    for (int i = 0; i < 2; i++)
#pragma unroll
        for (int j = 0; j < NT; j++)
#pragma unroll
            for (int t = 0; t < 4; t++) c[i][j][t] = 0.f;

    const int lrow = (lane & 7) | ((lane >> 3) & 1) << 3;
    const int lcol = (lane >> 4) * 8;

    auto compute = [&](int cc) {
        const uint32_t sb = sbase + (cc % NSTAGES) * BUFB;
#pragma unroll
        for (int k0 = 0; k0 < 32; k0 += 16) {
            uint32_t ah[2][4], al[2][4];
#pragma unroll
            for (int mt = 0; mt < 2; mt++) {
                const uint32_t ra = (uint32_t)(wm * 32 + mt * 16 + lrow) * PITCH + (k0 + lcol) * 2;
                LDM_X4(ah[mt], sb + AH_OFF + ra);
                if (NPROD == 3) LDM_X4(al[mt], sb + AL_OFF + ra);
            }
#pragma unroll
            for (int nt2 = 0; nt2 < NT2; nt2++) {
                uint32_t bh[4], bl[4];
                const uint32_t rb = (uint32_t)(wn * WNC + nt2 * 16 + lrow) * PITCH + (k0 + lcol) * 2;
                LDM_X4(bh, sb + BH_OFF + rb);
                if (NPROD >= 2) LDM_X4(bl, sb + BL_OFF + rb);
#pragma unroll
                for (int sel = 0; sel < 2; sel++) {
                    const int nt = nt2 * 2 + sel;
                    mma_f16(c[0][nt], ah[0], bh[sel], bh[2 + sel]);
                    mma_f16(c[1][nt], ah[1], bh[sel], bh[2 + sel]);
                }
                if (NPROD >= 2) {
#pragma unroll
                    for (int sel = 0; sel < 2; sel++) {
                        const int nt = nt2 * 2 + sel;
                        mma_f16(c[0][nt], ah[0], bl[sel], bl[2 + sel]);
                        mma_f16(c[1][nt], ah[1], bl[sel], bl[2 + sel]);
                    }
                }
                if (NPROD == 3) {
#pragma unroll
                    for (int sel = 0; sel < 2; sel++) {
                        const int nt = nt2 * 2 + sel;
                        mma_f16(c[0][nt], al[0], bh[sel], bh[2 + sel]);
                        mma_f16(c[1][nt], al[1], bh[sel], bh[2 + sel]);
                    }
                }
            }
        }
    };

    if (NSTAGES == 2) {
        issue(0);
        for (int cc = 0; cc < KC; cc++) {
            if (cc + 1 < KC) { issue(cc + 1); CP_WAIT(1); }
            else             { CP_WAIT(0); }
            __syncthreads();
            compute(cc);
            __syncthreads();
        }
    } else {
        issue(0);
        issue(1);
        for (int cc = 0; cc < KC; cc++) {
            if (cc < KC - 1) { CP_WAIT(1); } else { CP_WAIT(0); }
            __syncthreads();
            if (cc + 2 < KC) issue(cc + 2);
            compute(cc);
        }
    }

    // ---- epilogue ----
    const int qrow = lane >> 2;
    const int qcol = (lane & 3) * 2;
#pragma unroll
    for (int mt = 0; mt < 2; mt++) {
#pragma unroll
        for (int nt = 0; nt < NT; nt++) {
            const int row0 = m0 + wm * 32 + mt * 16 + qrow;
            const int col = n0 + wn * WNC + nt * 8 + qcol;
            const float* f = c[mt][nt];
#pragma unroll
            for (int h = 0; h < 2; h++) {
                const int row = row0 + h * 8;
                float v0 = f[2 * h], v1 = f[2 * h + 1];
                if (EP == 0) {
                    *(float2*)(C + (size_t)row * N + col) = make_float2(v0, v1);
                } else if (EP == 2) {
                    const float2 r2 = *(const float2*)(R + (size_t)row * N + col);
                    *(float2*)(C + (size_t)row * N + col) = make_float2(v0 + r2.x, v1 + r2.y);
                } else if (EP == 3) {
                    uint32_t hw, lw;
                    hsplit2(v0, v1, hw, lw);
                    *(uint32_t*)(Ch + (size_t)row * N + col) = hw;
                    *(uint32_t*)(Cl + (size_t)row * N + col) = lw;
                } else {
                    if (EP == 1) { v0 = fmaxf(v0, 0.f); v1 = fmaxf(v1, 0.f); }
                    *(uint32_t*)(Ch + (size_t)row * N + col) = packh2(v0, v1);
                }
            }
        }
    }
}

// ---------------------------------------------------------------------------
// elementwise split: fp32 -> hi/lo fp16
// ---------------------------------------------------------------------------
__global__ void split_k(const float* __restrict__ in, h16* __restrict__ oh,
                        h16* __restrict__ ol, size_t n4)
{
    const size_t i = (size_t)blockIdx.x * blockDim.x + threadIdx.x;
    if (i >= n4) return;
    const float4 v = ((const float4*)in)[i];
    uint32_t h0, l0, h1, l1;
    hsplit2(v.x, v.y, h0, l0);
    hsplit2(v.z, v.w, h1, l1);
    ((uint2*)oh)[i] = make_uint2(h0, h1);
    ((uint2*)ol)[i] = make_uint2(l0, l1);
}

// ---------------------------------------------------------------------------
// transpose + split: fp32 [R,C] -> hi/lo fp16 [C,R]
// ---------------------------------------------------------------------------
__global__ void tsplit_k(const float* __restrict__ in, h16* __restrict__ oh,
                         h16* __restrict__ ol, int Rr, int Cc, size_t sin, size_t sout)
{
    __shared__ float t[32][33];
    const int z = blockIdx.z;
    in += z * sin; oh += z * sout; ol += z * sout;
    const int c0 = blockIdx.x * 32, r0 = blockIdx.y * 32;
    const int tx = threadIdx.x, ty = threadIdx.y;
#pragma unroll
    for (int i = 0; i < 32; i += 8)
        t[ty + i][tx] = in[(size_t)(r0 + ty + i) * Cc + c0 + tx];
    __syncthreads();
#pragma unroll
    for (int i = 0; i < 32; i += 8) {
        const float x = t[tx][ty + i];
        const h16 hh = __float2half_rn(x);
        const size_t o = (size_t)(c0 + ty + i) * Rr + r0 + tx;
        oh[o] = hh;
        ol[o] = __float2half_rn(x - __half2float(hh));
    }
}

// ---------------------------------------------------------------------------
// transpose fp32 -> fp16 hi only, batched
// ---------------------------------------------------------------------------
__global__ void thalf_k(const float* __restrict__ in, h16* __restrict__ oh,
                        int Rr, int Cc, size_t sin, size_t sout)
{
    __shared__ float tbuf[32][33];
    const int z = blockIdx.z;
    in += z * sin; oh += z * sout;
    const int c0 = blockIdx.x * 32, r0 = blockIdx.y * 32;
    const int tx = threadIdx.x, ty = threadIdx.y;
#pragma unroll
    for (int i = 0; i < 32; i += 8)
        tbuf[ty + i][tx] = in[(size_t)(r0 + ty + i) * Cc + c0 + tx];
    __syncthreads();
#pragma unroll
    for (int i = 0; i < 32; i += 8)
        oh[(size_t)(c0 + ty + i) * Rr + r0 + tx] = __float2half_rn(tbuf[tx][ty + i]);
}

// ---------------------------------------------------------------------------
// softmax rows (n=2048), warp-shuffle reductions, hi-only fp16 out
// ---------------------------------------------------------------------------
__global__ void softmax_k(const float* __restrict__ S, h16* __restrict__ oh, int n)
{
    const size_t ro = (size_t)blockIdx.x * n;
    const float* row = S + ro;
    const int t = threadIdx.x;
    const int lane = t & 31, w = t >> 5;
    __shared__ float red[8];

    float v[8];
    {
        const float4 x0 = *(const float4*)(row + t * 8);
        const float4 x1 = *(const float4*)(row + t * 8 + 4);
        v[0] = x0.x; v[1] = x0.y; v[2] = x0.z; v[3] = x0.w;
        v[4] = x1.x; v[5] = x1.y; v[6] = x1.z; v[7] = x1.w;
    }
    float m = v[0];
#pragma unroll
    for (int i = 1; i < 8; i++) m = fmaxf(m, v[i]);
#pragma unroll
    for (int o = 16; o > 0; o >>= 1) m = fmaxf(m, __shfl_xor_sync(0xffffffffu, m, o));
    if (lane == 0) red[w] = m;
    __syncthreads();
    float M = red[0];
#pragma unroll
    for (int i = 1; i < 8; i++) M = fmaxf(M, red[i]);
    __syncthreads();

    float sum = 0.f;
#pragma unroll
    for (int i = 0; i < 8; i++) { v[i] = expf(v[i] - M); sum += v[i]; }
#pragma unroll
    for (int o = 16; o > 0; o >>= 1) sum += __shfl_xor_sync(0xffffffffu, sum, o);
    if (lane == 0) red[w] = sum;
    __syncthreads();
    float Sm = red[0];
#pragma unroll
    for (int i = 1; i < 8; i++) Sm += red[i];
    const float inv = 1.f / Sm;

    uint32_t hw[4];
#pragma unroll
    for (int i = 0; i < 4; i++)
        hw[i] = packh2(v[2 * i] * inv, v[2 * i + 1] * inv);
    *(uint4*)(oh + ro + t * 8) = make_uint4(hw[0], hw[1], hw[2], hw[3]);
}

// ---------------------------------------------------------------------------
extern "C" void kernel_launch(void* const* d_in, const int* in_sizes, int n_in,
                              void* d_out, int out_size)
{
    const float* x  = (const float*)d_in[0];
    const float* wq = (const float*)d_in[1];
    const float* wk = (const float*)d_in[2];
    const float* wv = (const float*)d_in[3];
    const float* wo = (const float*)d_in[4];
    const float* w1 = (const float*)d_in[5];
    const float* w2 = (const float*)d_in[6];
    float* out = (float*)d_out;

#define SYM(T, p, g) T p; cudaGetSymbolAddress((void**)&p, g)
    SYM(h16*, xh, g_xh); SYM(h16*, xl, g_xl);
    SYM(h16*, qh, g_qh); SYM(h16*, kh, g_kh); SYM(h16*, kl, g_kl);
    SYM(float*, v, g_v); SYM(h16*, vTh, g_vTh);
    SYM(float*, s, g_s); SYM(h16*, sh, g_sh);
    SYM(h16*, ah, g_ah); SYM(h16*, ph, g_ph); SYM(h16*, hh, g_hh);
    SYM(h16*, wqh, g_wqh); SYM(h16*, wql, g_wql);
    SYM(h16*, wkh, g_wkh); SYM(h16*, wkl, g_wkl);
    SYM(h16*, wvh, g_wvh); SYM(h16*, woh, g_woh);
    SYM(h16*, w1h, g_w1h); SYM(h16*, w2h, g_w2h);
#undef SYM

    // dynamic smem: 3 stages everywhere (TN=64 shrinks tiles under the 2-CTA cap)
    const int SM_X3_64 = 3 * (2 * ATILE + 2 * 64 * PITCH);   // 92160
    const int SM_X2_64 = 3 * (ATILE + 2 * 64 * PITCH);       // 61440
    const int SM_X1_64 = 3 * (ATILE + 64 * PITCH);           // 46080
    const int SM_X1_128 = 3 * (ATILE + 128 * PITCH);         // 61440
    cudaFuncSetAttribute(gemm_mma<4, 3, 64>,  cudaFuncAttributeMaxDynamicSharedMemorySize, SM_X3_64);
    cudaFuncSetAttribute(gemm_mma<3, 3, 64>,  cudaFuncAttributeMaxDynamicSharedMemorySize, SM_X3_64);
    cudaFuncSetAttribute(gemm_mma<0, 1, 64>,  cudaFuncAttributeMaxDynamicSharedMemorySize, SM_X1_64);
    cudaFuncSetAttribute(gemm_mma<0, 2, 64>,  cudaFuncAttributeMaxDynamicSharedMemorySize, SM_X2_64);
    cudaFuncSetAttribute(gemm_mma<4, 1, 64>,  cudaFuncAttributeMaxDynamicSharedMemorySize, SM_X1_64);
    cudaFuncSetAttribute(gemm_mma<1, 1, 128>, cudaFuncAttributeMaxDynamicSharedMemorySize, SM_X1_128);
    cudaFuncSetAttribute(gemm_mma<2, 1, 64>,  cudaFuncAttributeMaxDynamicSharedMemorySize, SM_X1_64);

    const size_t sSD = (size_t)SS * DD;
    const size_t sSS2 = (size_t)SS * SS;
    const dim3 tb(32, 8);

    // launches 0-4 (launch #5 = q GEMM for ncu -s 5 -c 1)
    split_k<<<(MM * DD / 4 + 255) / 256, 256>>>(x, xh, xl, (size_t)MM * DD / 4);
    tsplit_k<<<dim3(32, 32), tb>>>(wq, wqh, wql, DD, DD, 0, 0);
    tsplit_k<<<dim3(32, 32), tb>>>(wk, wkh, wkl, DD, DD, 0, 0);
    thalf_k<<<dim3(32, 32), tb>>>(wv, wvh, DD, DD, 0, 0);
    thalf_k<<<dim3(32, 32), tb>>>(wo, woh, DD, DD, 0, 0);

    // q projection (x3 compute, hi-only out) — profiled launch
    gemm_mma<4, 3, 64><<<dim3(16, 64), 256, SM_X3_64>>>(xh, xl, wqh, wql, nullptr, qh, nullptr, nullptr, MM, DD, DD, 0, 0, 0);
    // k projection (x3, split out)
    gemm_mma<3, 3, 64><<<dim3(16, 64), 256, SM_X3_64>>>(xh, xl, wkh, wkl, nullptr, kh, kl, nullptr, MM, DD, DD, 0, 0, 0);
    // v projection (x1, fp32 out)
    gemm_mma<0, 1, 64><<<dim3(16, 64), 256, SM_X1_64>>>(xh, nullptr, wvh, nullptr, v, nullptr, nullptr, nullptr, MM, DD, DD, 0, 0, 0);

    // remaining weights (hi-only)
    thalf_k<<<dim3(DFF_ / 32, DD / 32), tb>>>(w1, w1h, DD, DFF_, 0, 0);   // [DFF,D]
    thalf_k<<<dim3(DD / 32, DFF_ / 32), tb>>>(w2, w2h, DFF_, DD, 0, 0);   // [D,DFF]

    // vT per batch (hi-only)
    thalf_k<<<dim3(DD / 32, SS / 32, BB), tb>>>(v, vTh, SS, DD, sSD, sSD);

    // scores = q @ k^T (x2: A = q hi, B = k split; fp32 out)
    gemm_mma<0, 2, 64><<<dim3(32, 16, BB), 256, SM_X2_64>>>(qh, nullptr, kh, kl, s, nullptr, nullptr, nullptr, SS, SS, DD, sSD, sSD, sSS2);

    // softmax (hi out)
    softmax_k<<<MM, 256>>>(s, sh, SS);

    // attn = weights @ v (x1, hi out)
    gemm_mma<4, 1, 64><<<dim3(16, 16, BB), 256, SM_X1_64>>>(sh, nullptr, vTh, nullptr, nullptr, ah, nullptr, nullptr, SS, DD, SS, sSS2, sSD, sSD);

    // proj = attn @ wo (x1, hi out)
    gemm_mma<4, 1, 64><<<dim3(16, 64), 256, SM_X1_64>>>(ah, nullptr, woh, nullptr, nullptr, ph, nullptr, nullptr, MM, DD, DD, 0, 0, 0);

    // hidden = relu(proj @ w1) (x1, hi out)
    gemm_mma<1, 1, 128><<<dim3(32, 64), 256, SM_X1_128>>>(ph, nullptr, w1h, nullptr, nullptr, hh, nullptr, nullptr, MM, DFF_, DD, 0, 0, 0);

    // out = hidden @ w2 + x (x1, fp32 + residual)
    gemm_mma<2, 1, 64><<<dim3(16, 64), 256, SM_X1_64>>>(hh, nullptr, w2h, nullptr, out, nullptr, nullptr, x, MM, DD, DFF_, 0, 0, 0);
}

// round 14
// speedup vs baseline: 1.3176x; 1.0091x over previous
#include <cuda_runtime.h>
#include <cuda_fp16.h>
#include <cstdint>
#include <math.h>

// ---------------------------------------------------------------------------
// TinyTransformerBlock, sm_103 plain-target tensor path.
// R13: R12 + transposing epilogue (EP5) on v-projection -> writes vT[D,S] fp16
//      directly; g_v fp32 buffer and vT transpose kernel removed.
// ---------------------------------------------------------------------------

#define BB   4
#define SS   2048
#define DD   1024
#define DFF_ 4096
#define MM   (BB * SS)      // 8192

typedef __half h16;

// ---- scratch (bss) ----
__device__ h16 g_xh[(size_t)MM * DD], g_xl[(size_t)MM * DD];
__device__ h16 g_qh[(size_t)MM * DD];
__device__ h16 g_kh[(size_t)MM * DD], g_kl[(size_t)MM * DD];
__device__ h16 g_vTh[(size_t)MM * DD];
__device__ float g_s[(size_t)BB * SS * SS];
__device__ h16 g_sh[(size_t)BB * SS * SS];
__device__ h16 g_ah[(size_t)MM * DD];
__device__ h16 g_ph[(size_t)MM * DD];
__device__ h16 g_hh[(size_t)MM * DFF_];
__device__ h16 g_wqh[(size_t)DD * DD], g_wql[(size_t)DD * DD];
__device__ h16 g_wkh[(size_t)DD * DD], g_wkl[(size_t)DD * DD];
__device__ h16 g_wvh[(size_t)DD * DD];
__device__ h16 g_woh[(size_t)DD * DD];
__device__ h16 g_w1h[(size_t)DFF_ * DD];        // [DFF,D]
__device__ h16 g_w2h[(size_t)DD * DFF_];        // [D,DFF]

// ---------------------------------------------------------------------------
__device__ __forceinline__ uint32_t smem_u32(const void* p) {
    uint32_t a;
    asm("{ .reg .u64 t; cvta.to.shared.u64 t, %1; cvt.u32.u64 %0, t; }" : "=r"(a) : "l"(p));
    return a;
}

__device__ __forceinline__ uint32_t packh2(float x0, float x1) {
    __half2 t = __floats2half2_rn(x0, x1);
    return *(uint32_t*)&t;
}

__device__ __forceinline__ void hsplit2(float x0, float x1, uint32_t& h, uint32_t& l) {
    h = packh2(x0, x1);
    __half2 hv = *(__half2*)&h;
    float2 f = __half22float2(hv);
    l = packh2(x0 - f.x, x1 - f.y);
}

#define CP_ASYNC16(sa, gp) \
    asm volatile("cp.async.cg.shared.global [%0], [%1], 16;" :: "r"(sa), "l"(gp))
#define CP_COMMIT() asm volatile("cp.async.commit_group;")
#define CP_WAIT(n)  asm volatile("cp.async.wait_group %0;" :: "n"(n))

#define LDM_X4(r, sa) \
    asm volatile("ldmatrix.sync.aligned.m8n8.x4.shared.b16 {%0,%1,%2,%3}, [%4];" \
                 : "=r"((r)[0]), "=r"((r)[1]), "=r"((r)[2]), "=r"((r)[3]) : "r"(sa))

__device__ __forceinline__ void mma_f16(float* c, const uint32_t* a, uint32_t b0, uint32_t b1) {
    asm volatile(
        "mma.sync.aligned.m16n8k16.row.col.f32.f16.f16.f32 "
        "{%0,%1,%2,%3}, {%4,%5,%6,%7}, {%8,%9}, {%0,%1,%2,%3};"
        : "+f"(c[0]), "+f"(c[1]), "+f"(c[2]), "+f"(c[3])
        : "r"(a[0]), "r"(a[1]), "r"(a[2]), "r"(a[3]), "r"(b0), "r"(b1));
}

// ---------------------------------------------------------------------------
// fp16 split GEMM: C[M,N] = A[M,K] @ B[N,K]^T.
// NPROD=3: ah*bh + ah*bl + al*bh.  NPROD=2: ah*bh + ah*bl.  NPROD=1: ah*bh.
// TN in {64,128}: N-tile width (M-tile fixed 128).
// EP: 0 fp32; 1 relu+hi; 2 fp32+R; 3 split hi+lo; 4 hi;
//     5 transpose-fp16 (write Ch as per-batch [N, S] = vT; requires TN=64).
// ---------------------------------------------------------------------------
#define PITCH 80
#define ATILE (128 * PITCH)

template <int EP, int NPROD, int TN>
__global__ void __launch_bounds__(256, 2)
gemm_mma(const h16* __restrict__ Ah, const h16* __restrict__ Al,
         const h16* __restrict__ Bh, const h16* __restrict__ Bl,
         float* __restrict__ C, h16* __restrict__ Ch, h16* __restrict__ Cl,
         const float* __restrict__ R,
         int M, int N, int K, size_t sA, size_t sB, size_t sC)
{
    constexpr int BTILE = TN * PITCH;
    constexpr int AH_OFF = 0;
    constexpr int AL_OFF = ATILE;                               // NPROD==3 only
    constexpr int BH_OFF = (NPROD == 3 ? 2 : 1) * ATILE;
    constexpr int BL_OFF = BH_OFF + BTILE;                      // NPROD>=2 only
    constexpr int BUFB = (NPROD == 3 ? 2 : 1) * ATILE + (NPROD >= 2 ? 2 : 1) * BTILE;
    constexpr int NSTAGES = (3 * BUFB <= 94208) ? 3 : 2;
    constexpr int WNC = TN / 2;      // cols per wn half
    constexpr int NT2 = TN / 32;     // 16-col ldmatrix groups per warp
    constexpr int NT  = TN / 16;     // 8-col output tiles per warp
    static_assert(EP != 5 || TN == 64, "EP5 requires TN=64");

    extern __shared__ char smem_raw[];
    const uint32_t sbase = smem_u32(smem_raw);

    const int z = blockIdx.z;
    Ah += z * sA;
    if (NPROD == 3) Al += z * sA;
    Bh += z * sB;
    if (NPROD >= 2) Bl += z * sB;
    if (EP == 0 || EP == 2) C += z * sC;
    else { Ch += z * sC; if (EP == 3) Cl += z * sC; }

    const int n0 = blockIdx.x * TN;
    const int m0 = blockIdx.y * 128;
    const int tid = threadIdx.x;
    const int lane = tid & 31;
    const int warp = tid >> 5;
    const int wm = warp >> 1;        // m offset 32*wm
    const int wn = warp & 1;         // n offset WNC*wn

    const int KC = K / 32;
    const int lr = tid >> 2;             // 0..63
    const int lcb = (tid & 3) * 16;      // byte offset in 64B k-row

    auto issue = [&](int c) {
        const uint32_t sb = sbase + (c % NSTAGES) * BUFB;
        const size_t ke = (size_t)c * 32;
#pragma unroll
        for (int pass = 0; pass < 2; pass++) {
            const int r = lr + pass * 64;
            const uint32_t so = (uint32_t)r * PITCH + lcb;
            CP_ASYNC16(sb + AH_OFF + so, (const char*)(Ah + (size_t)(m0 + r) * K + ke) + lcb);
            if (NPROD == 3)
                CP_ASYNC16(sb + AL_OFF + so, (const char*)(Al + (size_t)(m0 + r) * K + ke) + lcb);
        }
#pragma unroll
        for (int pass = 0; pass < TN / 64; pass++) {
            const int r = lr + pass * 64;
            const uint32_t so = (uint32_t)r * PITCH + lcb;
            CP_ASYNC16(sb + BH_OFF + so, (const char*)(Bh + (size_t)(n0 + r) * K + ke) + lcb);
            if (NPROD >= 2)
                CP_ASYNC16(sb + BL_OFF + so, (const char*)(Bl + (size_t)(n0 + r) * K + ke) + lcb);
        }
        CP_COMMIT();
    };

    float c[2][NT][4];
#pragma unroll
    for (int i = 0; i < 2; i++)
#pragma unroll
        for (int j = 0; j < NT; j++)
#pragma unroll
            for (int t = 0; t < 4; t++) c[i][j][t] = 0.f;

    const int lrow = (lane & 7) | ((lane >> 3) & 1) << 3;
    const int lcol = (lane >> 4) * 8;

    auto compute = [&](int cc) {
        const uint32_t sb = sbase + (cc % NSTAGES) * BUFB;
#pragma unroll
        for (int k0 = 0; k0 < 32; k0 += 16) {
            uint32_t ah[2][4], al[2][4];
#pragma unroll
            for (int mt = 0; mt < 2; mt++) {
                const uint32_t ra = (uint32_t)(wm * 32 + mt * 16 + lrow) * PITCH + (k0 + lcol) * 2;
                LDM_X4(ah[mt], sb + AH_OFF + ra);
                if (NPROD == 3) LDM_X4(al[mt], sb + AL_OFF + ra);
            }
#pragma unroll
            for (int nt2 = 0; nt2 < NT2; nt2++) {
                uint32_t bh[4], bl[4];
                const uint32_t rb = (uint32_t)(wn * WNC + nt2 * 16 + lrow) * PITCH + (k0 + lcol) * 2;
                LDM_X4(bh, sb + BH_OFF + rb);
                if (NPROD >= 2) LDM_X4(bl, sb + BL_OFF + rb);
#pragma unroll
                for (int sel = 0; sel < 2; sel++) {
                    const int nt = nt2 * 2 + sel;
                    mma_f16(c[0][nt], ah[0], bh[sel], bh[2 + sel]);
                    mma_f16(c[1][nt], ah[1], bh[sel], bh[2 + sel]);
                }
                if (NPROD >= 2) {
#pragma unroll
                    for (int sel = 0; sel < 2; sel++) {
                        const int nt = nt2 * 2 + sel;
                        mma_f16(c[0][nt], ah[0], bl[sel], bl[2 + sel]);
                        mma_f16(c[1][nt], ah[1], bl[sel], bl[2 + sel]);
                    }
                }
                if (NPROD == 3) {
#pragma unroll
                    for (int sel = 0; sel < 2; sel++) {
                        const int nt = nt2 * 2 + sel;
                        mma_f16(c[0][nt], al[0], bh[sel], bh[2 + sel]);
                        mma_f16(c[1][nt], al[1], bh[sel], bh[2 + sel]);
                    }
                }
            }
        }
    };

    if (NSTAGES == 2) {
        issue(0);
        for (int cc = 0; cc < KC; cc++) {
            if (cc + 1 < KC) { issue(cc + 1); CP_WAIT(1); }
            else             { CP_WAIT(0); }
            __syncthreads();
            compute(cc);
            __syncthreads();
        }
    } else {
        issue(0);
        issue(1);
        for (int cc = 0; cc < KC; cc++) {
            if (cc < KC - 1) { CP_WAIT(1); } else { CP_WAIT(0); }
            __syncthreads();
            if (cc + 2 < KC) issue(cc + 2);
            compute(cc);
        }
    }

    const int qrow = lane >> 2;
    const int qcol = (lane & 3) * 2;

    if (EP == 5) {
        // ---- transposing epilogue: C tile [128 m x 64 n] -> vT[N, S] fp16 ----
        __syncthreads();                      // mainloop smem reads done
        h16* st = (h16*)smem_raw;             // staged transposed: st[n][m], pitch PM
        constexpr int PM = 136;               // 272B rows: 16B-aligned readback
#pragma unroll
        for (int mt = 0; mt < 2; mt++) {
#pragma unroll
            for (int nt = 0; nt < NT; nt++) {
                const int col = wn * WNC + nt * 8 + qcol;           // 0..63
                const float* f = c[mt][nt];
#pragma unroll
                for (int h = 0; h < 2; h++) {
                    const int row = wm * 32 + mt * 16 + qrow + h * 8;   // 0..127
                    st[(col + 0) * PM + row] = __float2half_rn(f[2 * h]);
                    st[(col + 1) * PM + row] = __float2half_rn(f[2 * h + 1]);
                }
            }
        }
        __syncthreads();
        const int batch = m0 >> 11;           // SS = 2048
        const int s_off = m0 & 2047;
        const int j = tid >> 2;               // 0..63 (d row within tile)
        const int i4 = (tid & 3) * 32;        // 0,32,64,96 (m offset)
        const uint4* src = (const uint4*)(st + j * PM + i4);
        uint4* dst = (uint4*)(Ch + (size_t)batch * ((size_t)SS * DD)
                              + (size_t)(n0 + j) * SS + s_off + i4);
#pragma unroll
        for (int u = 0; u < 4; u++) dst[u] = src[u];
        return;
    }

    // ---- standard epilogues ----
#pragma unroll
    for (int mt = 0; mt < 2; mt++) {
#pragma unroll
        for (int nt = 0; nt < NT; nt++) {
            const int row0 = m0 + wm * 32 + mt * 16 + qrow;
            const int col = n0 + wn * WNC + nt * 8 + qcol;
            const float* f = c[mt][nt];
#pragma unroll
            for (int h = 0; h < 2; h++) {
                const int row = row0 + h * 8;
                float v0 = f[2 * h], v1 = f[2 * h + 1];
                if (EP == 0) {
                    *(float2*)(C + (size_t)row * N + col) = make_float2(v0, v1);
                } else if (EP == 2) {
                    const float2 r2 = *(const float2*)(R + (size_t)row * N + col);
                    *(float2*)(C + (size_t)row * N + col) = make_float2(v0 + r2.x, v1 + r2.y);
                } else if (EP == 3) {
                    uint32_t hw, lw;
                    hsplit2(v0, v1, hw, lw);
                    *(uint32_t*)(Ch + (size_t)row * N + col) = hw;
                    *(uint32_t*)(Cl + (size_t)row * N + col) = lw;
                } else {
                    if (EP == 1) { v0 = fmaxf(v0, 0.f); v1 = fmaxf(v1, 0.f); }
                    *(uint32_t*)(Ch + (size_t)row * N + col) = packh2(v0, v1);
                }
            }
        }
    }
}

// ---------------------------------------------------------------------------
// elementwise split: fp32 -> hi/lo fp16
// ---------------------------------------------------------------------------
__global__ void split_k(const float* __restrict__ in, h16* __restrict__ oh,
                        h16* __restrict__ ol, size_t n4)
{
    const size_t i = (size_t)blockIdx.x * blockDim.x + threadIdx.x;
    if (i >= n4) return;
    const float4 v = ((const float4*)in)[i];
    uint32_t h0, l0, h1, l1;
    hsplit2(v.x, v.y, h0, l0);
    hsplit2(v.z, v.w, h1, l1);
    ((uint2*)oh)[i] = make_uint2(h0, h1);
    ((uint2*)ol)[i] = make_uint2(l0, l1);
}

// ---------------------------------------------------------------------------
// transpose + split: fp32 [R,C] -> hi/lo fp16 [C,R]
// ---------------------------------------------------------------------------
__global__ void tsplit_k(const float* __restrict__ in, h16* __restrict__ oh,
                         h16* __restrict__ ol, int Rr, int Cc, size_t sin, size_t sout)
{
    __shared__ float t[32][33];
    const int z = blockIdx.z;
    in += z * sin; oh += z * sout; ol += z * sout;
    const int c0 = blockIdx.x * 32, r0 = blockIdx.y * 32;
    const int tx = threadIdx.x, ty = threadIdx.y;
#pragma unroll
    for (int i = 0; i < 32; i += 8)
        t[ty + i][tx] = in[(size_t)(r0 + ty + i) * Cc + c0 + tx];
    __syncthreads();
#pragma unroll
    for (int i = 0; i < 32; i += 8) {
        const float x = t[tx][ty + i];
        const h16 hh = __float2half_rn(x);
        const size_t o = (size_t)(c0 + ty + i) * Rr + r0 + tx;
        oh[o] = hh;
        ol[o] = __float2half_rn(x - __half2float(hh));
    }
}

// ---------------------------------------------------------------------------
// transpose fp32 -> fp16 hi only, batched
// ---------------------------------------------------------------------------
__global__ void thalf_k(const float* __restrict__ in, h16* __restrict__ oh,
                        int Rr, int Cc, size_t sin, size_t sout)
{
    __shared__ float tbuf[32][33];
    const int z = blockIdx.z;
    in += z * sin; oh += z * sout;
    const int c0 = blockIdx.x * 32, r0 = blockIdx.y * 32;
    const int tx = threadIdx.x, ty = threadIdx.y;
#pragma unroll
    for (int i = 0; i < 32; i += 8)
        tbuf[ty + i][tx] = in[(size_t)(r0 + ty + i) * Cc + c0 + tx];
    __syncthreads();
#pragma unroll
    for (int i = 0; i < 32; i += 8)
        oh[(size_t)(c0 + ty + i) * Rr + r0 + tx] = __float2half_rn(tbuf[tx][ty + i]);
}

// ---------------------------------------------------------------------------
// softmax rows (n=2048), warp-shuffle reductions, hi-only fp16 out
// ---------------------------------------------------------------------------
__global__ void softmax_k(const float* __restrict__ S, h16* __restrict__ oh, int n)
{
    const size_t ro = (size_t)blockIdx.x * n;
    const float* row = S + ro;
    const int t = threadIdx.x;
    const int lane = t & 31, w = t >> 5;
    __shared__ float red[8];

    float v[8];
    {
        const float4 x0 = *(const float4*)(row + t * 8);
        const float4 x1 = *(const float4*)(row + t * 8 + 4);
        v[0] = x0.x; v[1] = x0.y; v[2] = x0.z; v[3] = x0.w;
        v[4] = x1.x; v[5] = x1.y; v[6] = x1.z; v[7] = x1.w;
    }
    float m = v[0];
#pragma unroll
    for (int i = 1; i < 8; i++) m = fmaxf(m, v[i]);
#pragma unroll
    for (int o = 16; o > 0; o >>= 1) m = fmaxf(m, __shfl_xor_sync(0xffffffffu, m, o));
    if (lane == 0) red[w] = m;
    __syncthreads();
    float M = red[0];
#pragma unroll
    for (int i = 1; i < 8; i++) M = fmaxf(M, red[i]);
    __syncthreads();

    float sum = 0.f;
#pragma unroll
    for (int i = 0; i < 8; i++) { v[i] = expf(v[i] - M); sum += v[i]; }
#pragma unroll
    for (int o = 16; o > 0; o >>= 1) sum += __shfl_xor_sync(0xffffffffu, sum, o);
    if (lane == 0) red[w] = sum;
    __syncthreads();
    float Sm = red[0];
#pragma unroll
    for (int i = 1; i < 8; i++) Sm += red[i];
    const float inv = 1.f / Sm;

    uint32_t hw[4];
#pragma unroll
    for (int i = 0; i < 4; i++)
        hw[i] = packh2(v[2 * i] * inv, v[2 * i + 1] * inv);
    *(uint4*)(oh + ro + t * 8) = make_uint4(hw[0], hw[1], hw[2], hw[3]);
}

// ---------------------------------------------------------------------------
extern "C" void kernel_launch(void* const* d_in, const int* in_sizes, int n_in,
                              void* d_out, int out_size)
{
    const float* x  = (const float*)d_in[0];
    const float* wq = (const float*)d_in[1];
    const float* wk = (const float*)d_in[2];
    const float* wv = (const float*)d_in[3];
    const float* wo = (const float*)d_in[4];
    const float* w1 = (const float*)d_in[5];
    const float* w2 = (const float*)d_in[6];
    float* out = (float*)d_out;

#define SYM(T, p, g) T p; cudaGetSymbolAddress((void**)&p, g)
    SYM(h16*, xh, g_xh); SYM(h16*, xl, g_xl);
    SYM(h16*, qh, g_qh); SYM(h16*, kh, g_kh); SYM(h16*, kl, g_kl);
    SYM(h16*, vTh, g_vTh);
    SYM(float*, s, g_s); SYM(h16*, sh, g_sh);
    SYM(h16*, ah, g_ah); SYM(h16*, ph, g_ph); SYM(h16*, hh, g_hh);
    SYM(h16*, wqh, g_wqh); SYM(h16*, wql, g_wql);
    SYM(h16*, wkh, g_wkh); SYM(h16*, wkl, g_wkl);
    SYM(h16*, wvh, g_wvh); SYM(h16*, woh, g_woh);
    SYM(h16*, w1h, g_w1h); SYM(h16*, w2h, g_w2h);
#undef SYM

    const int SM_X3_64 = 3 * (2 * ATILE + 2 * 64 * PITCH);   // 92160
    const int SM_X2_64 = 3 * (ATILE + 2 * 64 * PITCH);       // 61440
    const int SM_X1_64 = 3 * (ATILE + 64 * PITCH);           // 46080
    const int SM_X1_128 = 3 * (ATILE + 128 * PITCH);         // 61440
    cudaFuncSetAttribute(gemm_mma<4, 3, 64>,  cudaFuncAttributeMaxDynamicSharedMemorySize, SM_X3_64);
    cudaFuncSetAttribute(gemm_mma<3, 3, 64>,  cudaFuncAttributeMaxDynamicSharedMemorySize, SM_X3_64);
    cudaFuncSetAttribute(gemm_mma<5, 1, 64>,  cudaFuncAttributeMaxDynamicSharedMemorySize, SM_X1_64);
    cudaFuncSetAttribute(gemm_mma<0, 2, 64>,  cudaFuncAttributeMaxDynamicSharedMemorySize, SM_X2_64);
    cudaFuncSetAttribute(gemm_mma<4, 1, 64>,  cudaFuncAttributeMaxDynamicSharedMemorySize, SM_X1_64);
    cudaFuncSetAttribute(gemm_mma<1, 1, 128>, cudaFuncAttributeMaxDynamicSharedMemorySize, SM_X1_128);
    cudaFuncSetAttribute(gemm_mma<2, 1, 64>,  cudaFuncAttributeMaxDynamicSharedMemorySize, SM_X1_64);

    const size_t sSD = (size_t)SS * DD;
    const size_t sSS2 = (size_t)SS * SS;
    const dim3 tb(32, 8);

    // launches 0-4
    split_k<<<(MM * DD / 4 + 255) / 256, 256>>>(x, xh, xl, (size_t)MM * DD / 4);
    tsplit_k<<<dim3(32, 32), tb>>>(wq, wqh, wql, DD, DD, 0, 0);
    tsplit_k<<<dim3(32, 32), tb>>>(wk, wkh, wkl, DD, DD, 0, 0);
    thalf_k<<<dim3(32, 32), tb>>>(wv, wvh, DD, DD, 0, 0);
    thalf_k<<<dim3(32, 32), tb>>>(wo, woh, DD, DD, 0, 0);

    // q projection (x3 compute, hi-only out)
    gemm_mma<4, 3, 64><<<dim3(16, 64), 256, SM_X3_64>>>(xh, xl, wqh, wql, nullptr, qh, nullptr, nullptr, MM, DD, DD, 0, 0, 0);
    // k projection (x3, split out)
    gemm_mma<3, 3, 64><<<dim3(16, 64), 256, SM_X3_64>>>(xh, xl, wkh, wkl, nullptr, kh, kl, nullptr, MM, DD, DD, 0, 0, 0);
    // v projection (x1) -> writes vT[D,S] fp16 directly (EP5)
    gemm_mma<5, 1, 64><<<dim3(16, 64), 256, SM_X1_64>>>(xh, nullptr, wvh, nullptr, nullptr, vTh, nullptr, nullptr, MM, DD, DD, 0, 0, 0);

    // remaining weights (hi-only)
    thalf_k<<<dim3(DFF_ / 32, DD / 32), tb>>>(w1, w1h, DD, DFF_, 0, 0);   // [DFF,D]
    thalf_k<<<dim3(DD / 32, DFF_ / 32), tb>>>(w2, w2h, DFF_, DD, 0, 0);   // [D,DFF]

    // scores = q @ k^T (x2: A = q hi, B = k split; fp32 out)
    gemm_mma<0, 2, 64><<<dim3(32, 16, BB), 256, SM_X2_64>>>(qh, nullptr, kh, kl, s, nullptr, nullptr, nullptr, SS, SS, DD, sSD, sSD, sSS2);

    // softmax (hi out)
    softmax_k<<<MM, 256>>>(s, sh, SS);

    // attn = weights @ v (x1, hi out)
    gemm_mma<4, 1, 64><<<dim3(16, 16, BB), 256, SM_X1_64>>>(sh, nullptr, vTh, nullptr, nullptr, ah, nullptr, nullptr, SS, DD, SS, sSS2, sSD, sSD);

    // proj = attn @ wo (x1, hi out)
    gemm_mma<4, 1, 64><<<dim3(16, 64), 256, SM_X1_64>>>(ah, nullptr, woh, nullptr, nullptr, ph, nullptr, nullptr, MM, DD, DD, 0, 0, 0);

    // hidden = relu(proj @ w1) (x1, hi out)
    gemm_mma<1, 1, 128><<<dim3(32, 64), 256, SM_X1_128>>>(ph, nullptr, w1h, nullptr, nullptr, hh, nullptr, nullptr, MM, DFF_, DD, 0, 0, 0);

    // out = hidden @ w2 + x (x1, fp32 + residual)
    gemm_mma<2, 1, 64><<<dim3(16, 64), 256, SM_X1_64>>>(hh, nullptr, w2h, nullptr, out, nullptr, nullptr, x, MM, DD, DFF_, 0, 0, 0);
}

// round 16
// speedup vs baseline: 1.3252x; 1.0057x over previous
#include <cuda_runtime.h>
#include <cuda_fp16.h>
#include <cstdint>
#include <math.h>

// ---------------------------------------------------------------------------
// TinyTransformerBlock, sm_103 plain-target tensor path.
// R14: R13 + fast softmax (__expf, MLP-4, warp reductions) + merged weight prep.
// ---------------------------------------------------------------------------

#define BB   4
#define SS   2048
#define DD   1024
#define DFF_ 4096
#define MM   (BB * SS)      // 8192

typedef __half h16;

// ---- scratch (bss) ----
__device__ h16 g_xh[(size_t)MM * DD], g_xl[(size_t)MM * DD];
__device__ h16 g_qh[(size_t)MM * DD];
__device__ h16 g_kh[(size_t)MM * DD], g_kl[(size_t)MM * DD];
__device__ h16 g_vTh[(size_t)MM * DD];
__device__ float g_s[(size_t)BB * SS * SS];
__device__ h16 g_sh[(size_t)BB * SS * SS];
__device__ h16 g_ah[(size_t)MM * DD];
__device__ h16 g_ph[(size_t)MM * DD];
__device__ h16 g_hh[(size_t)MM * DFF_];
__device__ h16 g_wqh[(size_t)DD * DD], g_wql[(size_t)DD * DD];
__device__ h16 g_wkh[(size_t)DD * DD], g_wkl[(size_t)DD * DD];
__device__ h16 g_wvh[(size_t)DD * DD];
__device__ h16 g_woh[(size_t)DD * DD];
__device__ h16 g_w1h[(size_t)DFF_ * DD];        // [DFF,D]
__device__ h16 g_w2h[(size_t)DD * DFF_];        // [D,DFF]

// ---------------------------------------------------------------------------
__device__ __forceinline__ uint32_t smem_u32(const void* p) {
    uint32_t a;
    asm("{ .reg .u64 t; cvta.to.shared.u64 t, %1; cvt.u32.u64 %0, t; }" : "=r"(a) : "l"(p));
    return a;
}

__device__ __forceinline__ uint32_t packh2(float x0, float x1) {
    __half2 t = __floats2half2_rn(x0, x1);
    return *(uint32_t*)&t;
}

__device__ __forceinline__ void hsplit2(float x0, float x1, uint32_t& h, uint32_t& l) {
    h = packh2(x0, x1);
    __half2 hv = *(__half2*)&h;
    float2 f = __half22float2(hv);
    l = packh2(x0 - f.x, x1 - f.y);
}

#define CP_ASYNC16(sa, gp) \
    asm volatile("cp.async.cg.shared.global [%0], [%1], 16;" :: "r"(sa), "l"(gp))
#define CP_COMMIT() asm volatile("cp.async.commit_group;")
#define CP_WAIT(n)  asm volatile("cp.async.wait_group %0;" :: "n"(n))

#define LDM_X4(r, sa) \
    asm volatile("ldmatrix.sync.aligned.m8n8.x4.shared.b16 {%0,%1,%2,%3}, [%4];" \
                 : "=r"((r)[0]), "=r"((r)[1]), "=r"((r)[2]), "=r"((r)[3]) : "r"(sa))

__device__ __forceinline__ void mma_f16(float* c, const uint32_t* a, uint32_t b0, uint32_t b1) {
    asm volatile(
        "mma.sync.aligned.m16n8k16.row.col.f32.f16.f16.f32 "
        "{%0,%1,%2,%3}, {%4,%5,%6,%7}, {%8,%9}, {%0,%1,%2,%3};"
        : "+f"(c[0]), "+f"(c[1]), "+f"(c[2]), "+f"(c[3])
        : "r"(a[0]), "r"(a[1]), "r"(a[2]), "r"(a[3]), "r"(b0), "r"(b1));
}

// ---------------------------------------------------------------------------
// fp16 split GEMM: C[M,N] = A[M,K] @ B[N,K]^T.
// NPROD=3: ah*bh + ah*bl + al*bh.  NPROD=2: ah*bh + ah*bl.  NPROD=1: ah*bh.
// TN in {64,128}: N-tile width (M-tile fixed 128).
// EP: 0 fp32; 1 relu+hi; 2 fp32+R; 3 split hi+lo; 4 hi;
//     5 transpose-fp16 (write Ch as per-batch [N, S] = vT; requires TN=64).
// ---------------------------------------------------------------------------
#define PITCH 80
#define ATILE (128 * PITCH)

template <int EP, int NPROD, int TN>
__global__ void __launch_bounds__(256, 2)
gemm_mma(const h16* __restrict__ Ah, const h16* __restrict__ Al,
         const h16* __restrict__ Bh, const h16* __restrict__ Bl,
         float* __restrict__ C, h16* __restrict__ Ch, h16* __restrict__ Cl,
         const float* __restrict__ R,
         int M, int N, int K, size_t sA, size_t sB, size_t sC)
{
    constexpr int BTILE = TN * PITCH;
    constexpr int AH_OFF = 0;
    constexpr int AL_OFF = ATILE;                               // NPROD==3 only
    constexpr int BH_OFF = (NPROD == 3 ? 2 : 1) * ATILE;
    constexpr int BL_OFF = BH_OFF + BTILE;                      // NPROD>=2 only
    constexpr int BUFB = (NPROD == 3 ? 2 : 1) * ATILE + (NPROD >= 2 ? 2 : 1) * BTILE;
    constexpr int NSTAGES = (3 * BUFB <= 94208) ? 3 : 2;
    constexpr int WNC = TN / 2;      // cols per wn half
    constexpr int NT2 = TN / 32;     // 16-col ldmatrix groups per warp
    constexpr int NT  = TN / 16;     // 8-col output tiles per warp
    static_assert(EP != 5 || TN == 64, "EP5 requires TN=64");

    extern __shared__ char smem_raw[];
    const uint32_t sbase = smem_u32(smem_raw);

    const int z = blockIdx.z;
    Ah += z * sA;
    if (NPROD == 3) Al += z * sA;
    Bh += z * sB;
    if (NPROD >= 2) Bl += z * sB;
    if (EP == 0 || EP == 2) C += z * sC;
    else { Ch += z * sC; if (EP == 3) Cl += z * sC; }

    const int n0 = blockIdx.x * TN;
    const int m0 = blockIdx.y * 128;
    const int tid = threadIdx.x;
    const int lane = tid & 31;
    const int warp = tid >> 5;
    const int wm = warp >> 1;        // m offset 32*wm
    const int wn = warp & 1;         // n offset WNC*wn

    const int KC = K / 32;
    const int lr = tid >> 2;             // 0..63
    const int lcb = (tid & 3) * 16;      // byte offset in 64B k-row

    auto issue = [&](int c) {
        const uint32_t sb = sbase + (c % NSTAGES) * BUFB;
        const size_t ke = (size_t)c * 32;
#pragma unroll
        for (int pass = 0; pass < 2; pass++) {
            const int r = lr + pass * 64;
            const uint32_t so = (uint32_t)r * PITCH + lcb;
            CP_ASYNC16(sb + AH_OFF + so, (const char*)(Ah + (size_t)(m0 + r) * K + ke) + lcb);
            if (NPROD == 3)
                CP_ASYNC16(sb + AL_OFF + so, (const char*)(Al + (size_t)(m0 + r) * K + ke) + lcb);
        }
#pragma unroll
        for (int pass = 0; pass < TN / 64; pass++) {
            const int r = lr + pass * 64;
            const uint32_t so = (uint32_t)r * PITCH + lcb;
            CP_ASYNC16(sb + BH_OFF + so, (const char*)(Bh + (size_t)(n0 + r) * K + ke) + lcb);
            if (NPROD >= 2)
                CP_ASYNC16(sb + BL_OFF + so, (const char*)(Bl + (size_t)(n0 + r) * K + ke) + lcb);
        }
        CP_COMMIT();
    };

    float c[2][NT][4];
#pragma unroll
    for (int i = 0; i < 2; i++)
#pragma unroll
        for (int j = 0; j < NT; j++)
#pragma unroll
            for (int t = 0; t < 4; t++) c[i][j][t] = 0.f;

    const int lrow = (lane & 7) | ((lane >> 3) & 1) << 3;
    const int lcol = (lane >> 4) * 8;

    auto compute = [&](int cc) {
        const uint32_t sb = sbase + (cc % NSTAGES) * BUFB;
#pragma unroll
        for (int k0 = 0; k0 < 32; k0 += 16) {
            uint32_t ah[2][4], al[2][4];
#pragma unroll
            for (int mt = 0; mt < 2; mt++) {
                const uint32_t ra = (uint32_t)(wm * 32 + mt * 16 + lrow) * PITCH + (k0 + lcol) * 2;
                LDM_X4(ah[mt], sb + AH_OFF + ra);
                if (NPROD == 3) LDM_X4(al[mt], sb + AL_OFF + ra);
            }
#pragma unroll
            for (int nt2 = 0; nt2 < NT2; nt2++) {
                uint32_t bh[4], bl[4];
                const uint32_t rb = (uint32_t)(wn * WNC + nt2 * 16 + lrow) * PITCH + (k0 + lcol) * 2;
                LDM_X4(bh, sb + BH_OFF + rb);
                if (NPROD >= 2) LDM_X4(bl, sb + BL_OFF + rb);
#pragma unroll
                for (int sel = 0; sel < 2; sel++) {
                    const int nt = nt2 * 2 + sel;
                    mma_f16(c[0][nt], ah[0], bh[sel], bh[2 + sel]);
                    mma_f16(c[1][nt], ah[1], bh[sel], bh[2 + sel]);
                }
                if (NPROD >= 2) {
#pragma unroll
                    for (int sel = 0; sel < 2; sel++) {
                        const int nt = nt2 * 2 + sel;
                        mma_f16(c[0][nt], ah[0], bl[sel], bl[2 + sel]);
                        mma_f16(c[1][nt], ah[1], bl[sel], bl[2 + sel]);
                    }
                }
                if (NPROD == 3) {
#pragma unroll
                    for (int sel = 0; sel < 2; sel++) {
                        const int nt = nt2 * 2 + sel;
                        mma_f16(c[0][nt], al[0], bh[sel], bh[2 + sel]);
                        mma_f16(c[1][nt], al[1], bh[sel], bh[2 + sel]);
                    }
                }
            }
        }
    };

    if (NSTAGES == 2) {
        issue(0);
        for (int cc = 0; cc < KC; cc++) {
            if (cc + 1 < KC) { issue(cc + 1); CP_WAIT(1); }
            else             { CP_WAIT(0); }
            __syncthreads();
            compute(cc);
            __syncthreads();
        }
    } else {
        issue(0);
        issue(1);
        for (int cc = 0; cc < KC; cc++) {
            if (cc < KC - 1) { CP_WAIT(1); } else { CP_WAIT(0); }
            __syncthreads();
            if (cc + 2 < KC) issue(cc + 2);
            compute(cc);
        }
    }

    const int qrow = lane >> 2;
    const int qcol = (lane & 3) * 2;

    if (EP == 5) {
        // ---- transposing epilogue: C tile [128 m x 64 n] -> vT[N, S] fp16 ----
        __syncthreads();
        h16* st = (h16*)smem_raw;
        constexpr int PM = 136;
#pragma unroll
        for (int mt = 0; mt < 2; mt++) {
#pragma unroll
            for (int nt = 0; nt < NT; nt++) {
                const int col = wn * WNC + nt * 8 + qcol;
                const float* f = c[mt][nt];
#pragma unroll
                for (int h = 0; h < 2; h++) {
                    const int row = wm * 32 + mt * 16 + qrow + h * 8;
                    st[(col + 0) * PM + row] = __float2half_rn(f[2 * h]);
                    st[(col + 1) * PM + row] = __float2half_rn(f[2 * h + 1]);
                }
            }
        }
        __syncthreads();
        const int batch = m0 >> 11;
        const int s_off = m0 & 2047;
        const int j = tid >> 2;
        const int i4 = (tid & 3) * 32;
        const uint4* src = (const uint4*)(st + j * PM + i4);
        uint4* dst = (uint4*)(Ch + (size_t)batch * ((size_t)SS * DD)
                              + (size_t)(n0 + j) * SS + s_off + i4);
#pragma unroll
        for (int u = 0; u < 4; u++) dst[u] = src[u];
        return;
    }

    // ---- standard epilogues ----
#pragma unroll
    for (int mt = 0; mt < 2; mt++) {
#pragma unroll
        for (int nt = 0; nt < NT; nt++) {
            const int row0 = m0 + wm * 32 + mt * 16 + qrow;
            const int col = n0 + wn * WNC + nt * 8 + qcol;
            const float* f = c[mt][nt];
#pragma unroll
            for (int h = 0; h < 2; h++) {
                const int row = row0 + h * 8;
                float v0 = f[2 * h], v1 = f[2 * h + 1];
                if (EP == 0) {
                    *(float2*)(C + (size_t)row * N + col) = make_float2(v0, v1);
                } else if (EP == 2) {
                    const float2 r2 = *(const float2*)(R + (size_t)row * N + col);
                    *(float2*)(C + (size_t)row * N + col) = make_float2(v0 + r2.x, v1 + r2.y);
                } else if (EP == 3) {
                    uint32_t hw, lw;
                    hsplit2(v0, v1, hw, lw);
                    *(uint32_t*)(Ch + (size_t)row * N + col) = hw;
                    *(uint32_t*)(Cl + (size_t)row * N + col) = lw;
                } else {
                    if (EP == 1) { v0 = fmaxf(v0, 0.f); v1 = fmaxf(v1, 0.f); }
                    *(uint32_t*)(Ch + (size_t)row * N + col) = packh2(v0, v1);
                }
            }
        }
    }
}

// ---------------------------------------------------------------------------
// elementwise split: fp32 -> hi/lo fp16
// ---------------------------------------------------------------------------
__global__ void split_k(const float* __restrict__ in, h16* __restrict__ oh,
                        h16* __restrict__ ol, size_t n4)
{
    const size_t i = (size_t)blockIdx.x * blockDim.x + threadIdx.x;
    if (i >= n4) return;
    const float4 v = ((const float4*)in)[i];
    uint32_t h0, l0, h1, l1;
    hsplit2(v.x, v.y, h0, l0);
    hsplit2(v.z, v.w, h1, l1);
    ((uint2*)oh)[i] = make_uint2(h0, h1);
    ((uint2*)ol)[i] = make_uint2(l0, l1);
}

// ---------------------------------------------------------------------------
// merged weight prep: z=0 wq->split(wqh,wql); z=1 wk->split; z=2 wv->hi; z=3 wo->hi
// All are [DD,DD] transposed to [N,K].
// ---------------------------------------------------------------------------
__global__ void prep4_k(const float* __restrict__ wq, const float* __restrict__ wk,
                        const float* __restrict__ wv, const float* __restrict__ wo,
                        h16* __restrict__ wqh, h16* __restrict__ wql,
                        h16* __restrict__ wkh, h16* __restrict__ wkl,
                        h16* __restrict__ wvh, h16* __restrict__ woh)
{
    __shared__ float tbuf[32][33];
    const int z = blockIdx.z;
    const float* in = (z == 0) ? wq : (z == 1) ? wk : (z == 2) ? wv : wo;
    h16* oh = (z == 0) ? wqh : (z == 1) ? wkh : (z == 2) ? wvh : woh;
    h16* ol = (z == 0) ? wql : wkl;    // used only for z<2

    const int c0 = blockIdx.x * 32, r0 = blockIdx.y * 32;
    const int tx = threadIdx.x, ty = threadIdx.y;
#pragma unroll
    for (int i = 0; i < 32; i += 8)
        tbuf[ty + i][tx] = in[(size_t)(r0 + ty + i) * DD + c0 + tx];
    __syncthreads();
#pragma unroll
    for (int i = 0; i < 32; i += 8) {
        const float x = tbuf[tx][ty + i];
        const h16 hh = __float2half_rn(x);
        const size_t o = (size_t)(c0 + ty + i) * DD + r0 + tx;
        oh[o] = hh;
        if (z < 2) ol[o] = __float2half_rn(x - __half2float(hh));
    }
}

// ---------------------------------------------------------------------------
// transpose fp32 -> fp16 hi only, batched
// ---------------------------------------------------------------------------
__global__ void thalf_k(const float* __restrict__ in, h16* __restrict__ oh,
                        int Rr, int Cc, size_t sin, size_t sout)
{
    __shared__ float tbuf[32][33];
    const int z = blockIdx.z;
    in += z * sin; oh += z * sout;
    const int c0 = blockIdx.x * 32, r0 = blockIdx.y * 32;
    const int tx = threadIdx.x, ty = threadIdx.y;
#pragma unroll
    for (int i = 0; i < 32; i += 8)
        tbuf[ty + i][tx] = in[(size_t)(r0 + ty + i) * Cc + c0 + tx];
    __syncthreads();
#pragma unroll
    for (int i = 0; i < 32; i += 8)
        oh[(size_t)(c0 + ty + i) * Rr + r0 + tx] = __float2half_rn(tbuf[tx][ty + i]);
}

// ---------------------------------------------------------------------------
// softmax rows (n=2048): 128 threads, 16 elems/thread (MLP 4), __expf,
// warp-shuffle + 4-slot reductions, hi-only fp16 out.
// ---------------------------------------------------------------------------
__global__ void softmax_k(const float* __restrict__ S, h16* __restrict__ oh, int n)
{
    const size_t ro = (size_t)blockIdx.x * n;
    const float4* row4 = (const float4*)(S + ro);
    const int t = threadIdx.x;          // 0..127
    const int lane = t & 31, w = t >> 5;
    __shared__ float red[4];

    float v[16];
#pragma unroll
    for (int i = 0; i < 4; i++) {
        const float4 x = row4[i * 128 + t];
        v[4 * i + 0] = x.x; v[4 * i + 1] = x.y;
        v[4 * i + 2] = x.z; v[4 * i + 3] = x.w;
    }

    float m = v[0];
#pragma unroll
    for (int i = 1; i < 16; i++) m = fmaxf(m, v[i]);
#pragma unroll
    for (int o = 16; o > 0; o >>= 1) m = fmaxf(m, __shfl_xor_sync(0xffffffffu, m, o));
    if (lane == 0) red[w] = m;
    __syncthreads();
    const float M = fmaxf(fmaxf(red[0], red[1]), fmaxf(red[2], red[3]));
    __syncthreads();

    float sum = 0.f;
#pragma unroll
    for (int i = 0; i < 16; i++) { v[i] = __expf(v[i] - M); sum += v[i]; }
#pragma unroll
    for (int o = 16; o > 0; o >>= 1) sum += __shfl_xor_sync(0xffffffffu, sum, o);
    if (lane == 0) red[w] = sum;
    __syncthreads();
    const float inv = 1.f / (red[0] + red[1] + red[2] + red[3]);

    uint2* out2 = (uint2*)(oh + ro);
#pragma unroll
    for (int i = 0; i < 4; i++) {
        out2[i * 128 + t] = make_uint2(packh2(v[4 * i] * inv, v[4 * i + 1] * inv),
                                       packh2(v[4 * i + 2] * inv, v[4 * i + 3] * inv));
    }
}

// ---------------------------------------------------------------------------
extern "C" void kernel_launch(void* const* d_in, const int* in_sizes, int n_in,
                              void* d_out, int out_size)
{
    const float* x  = (const float*)d_in[0];
    const float* wq = (const float*)d_in[1];
    const float* wk = (const float*)d_in[2];
    const float* wv = (const float*)d_in[3];
    const float* wo = (const float*)d_in[4];
    const float* w1 = (const float*)d_in[5];
    const float* w2 = (const float*)d_in[6];
    float* out = (float*)d_out;

#define SYM(T, p, g) T p; cudaGetSymbolAddress((void**)&p, g)
    SYM(h16*, xh, g_xh); SYM(h16*, xl, g_xl);
    SYM(h16*, qh, g_qh); SYM(h16*, kh, g_kh); SYM(h16*, kl, g_kl);
    SYM(h16*, vTh, g_vTh);
    SYM(float*, s, g_s); SYM(h16*, sh, g_sh);
    SYM(h16*, ah, g_ah); SYM(h16*, ph, g_ph); SYM(h16*, hh, g_hh);
    SYM(h16*, wqh, g_wqh); SYM(h16*, wql, g_wql);
    SYM(h16*, wkh, g_wkh); SYM(h16*, wkl, g_wkl);
    SYM(h16*, wvh, g_wvh); SYM(h16*, woh, g_woh);
    SYM(h16*, w1h, g_w1h); SYM(h16*, w2h, g_w2h);
#undef SYM

    const int SM_X3_64 = 3 * (2 * ATILE + 2 * 64 * PITCH);   // 92160
    const int SM_X2_64 = 3 * (ATILE + 2 * 64 * PITCH);       // 61440
    const int SM_X1_64 = 3 * (ATILE + 64 * PITCH);           // 46080
    const int SM_X1_128 = 3 * (ATILE + 128 * PITCH);         // 61440
    cudaFuncSetAttribute(gemm_mma<4, 3, 64>,  cudaFuncAttributeMaxDynamicSharedMemorySize, SM_X3_64);
    cudaFuncSetAttribute(gemm_mma<3, 3, 64>,  cudaFuncAttributeMaxDynamicSharedMemorySize, SM_X3_64);
    cudaFuncSetAttribute(gemm_mma<5, 1, 64>,  cudaFuncAttributeMaxDynamicSharedMemorySize, SM_X1_64);
    cudaFuncSetAttribute(gemm_mma<0, 2, 64>,  cudaFuncAttributeMaxDynamicSharedMemorySize, SM_X2_64);
    cudaFuncSetAttribute(gemm_mma<4, 1, 64>,  cudaFuncAttributeMaxDynamicSharedMemorySize, SM_X1_64);
    cudaFuncSetAttribute(gemm_mma<1, 1, 128>, cudaFuncAttributeMaxDynamicSharedMemorySize, SM_X1_128);
    cudaFuncSetAttribute(gemm_mma<2, 1, 64>,  cudaFuncAttributeMaxDynamicSharedMemorySize, SM_X1_64);

    const size_t sSD = (size_t)SS * DD;
    const size_t sSS2 = (size_t)SS * SS;
    const dim3 tb(32, 8);

    // prep: launches 0-3
    split_k<<<(MM * DD / 4 + 255) / 256, 256>>>(x, xh, xl, (size_t)MM * DD / 4);
    prep4_k<<<dim3(32, 32, 4), tb>>>(wq, wk, wv, wo, wqh, wql, wkh, wkl, wvh, woh);
    thalf_k<<<dim3(DFF_ / 32, DD / 32), tb>>>(w1, w1h, DD, DFF_, 0, 0);   // [DFF,D]
    thalf_k<<<dim3(DD / 32, DFF_ / 32), tb>>>(w2, w2h, DFF_, DD, 0, 0);   // [D,DFF]

    // q projection (x3 compute, hi-only out) — launch 4
    gemm_mma<4, 3, 64><<<dim3(16, 64), 256, SM_X3_64>>>(xh, xl, wqh, wql, nullptr, qh, nullptr, nullptr, MM, DD, DD, 0, 0, 0);
    // k projection (x3, split out) — launch 5, profiled
    gemm_mma<3, 3, 64><<<dim3(16, 64), 256, SM_X3_64>>>(xh, xl, wkh, wkl, nullptr, kh, kl, nullptr, MM, DD, DD, 0, 0, 0);
    // v projection (x1) -> writes vT[D,S] fp16 directly (EP5)
    gemm_mma<5, 1, 64><<<dim3(16, 64), 256, SM_X1_64>>>(xh, nullptr, wvh, nullptr, nullptr, vTh, nullptr, nullptr, MM, DD, DD, 0, 0, 0);

    // scores = q @ k^T (x2: A = q hi, B = k split; fp32 out)
    gemm_mma<0, 2, 64><<<dim3(32, 16, BB), 256, SM_X2_64>>>(qh, nullptr, kh, kl, s, nullptr, nullptr, nullptr, SS, SS, DD, sSD, sSD, sSS2);

    // softmax (hi out)
    softmax_k<<<MM, 128>>>(s, sh, SS);

    // attn = weights @ v (x1, hi out)
    gemm_mma<4, 1, 64><<<dim3(16, 16, BB), 256, SM_X1_64>>>(sh, nullptr, vTh, nullptr, nullptr, ah, nullptr, nullptr, SS, DD, SS, sSS2, sSD, sSD);

    // proj = attn @ wo (x1, hi out)
    gemm_mma<4, 1, 64><<<dim3(16, 64), 256, SM_X1_64>>>(ah, nullptr, woh, nullptr, nullptr, ph, nullptr, nullptr, MM, DD, DD, 0, 0, 0);

    // hidden = relu(proj @ w1) (x1, hi out)
    gemm_mma<1, 1, 128><<<dim3(32, 64), 256, SM_X1_128>>>(ph, nullptr, w1h, nullptr, nullptr, hh, nullptr, nullptr, MM, DFF_, DD, 0, 0, 0);

    // out = hidden @ w2 + x (x1, fp32 + residual)
    gemm_mma<2, 1, 64><<<dim3(16, 64), 256, SM_X1_64>>>(hh, nullptr, w2h, nullptr, out, nullptr, nullptr, x, MM, DD, DFF_, 0, 0, 0);
}